// round 10
// baseline (speedup 1.0000x reference)
#include <cuda_runtime.h>
#include <cuda_fp16.h>

// Problem constants
#define SS   110592          // 48^3
#define NT   221184          // NB*SS tokens

// Scratch (device globals; no allocation allowed) — all intermediates fp16
__device__ __half g_xe [NT * 128];            // pos-embedded input (residual 1)
__device__ __half g_o  [(size_t)NT * 384];    // attention outputs, 3 axes
// fp16 weights: [0,147456) qkv blocks (3 axes x [384][128]), [147456,196608)
// wout_cat (128 rows x 384), [196608,212992) w1, [212992,229376) w2
__device__ __half g_wh [229376];

// ---------------------------------------------------------------------------
// helpers
// ---------------------------------------------------------------------------
__device__ __forceinline__ void cpa16_s(unsigned d, const void* s) {
    asm volatile("cp.async.cg.shared.global [%0], [%1], 16;" :: "r"(d), "l"(s));
}
#define CP_COMMIT() asm volatile("cp.async.commit_group;")
#define CP_WAIT1()  asm volatile("cp.async.wait_group 1;")
#define CP_WAIT0()  asm volatile("cp.async.wait_group 0;")

#define LDSM4(r, addr) \
    asm volatile("ldmatrix.sync.aligned.m8n8.x4.shared.b16 {%0,%1,%2,%3}, [%4];" \
        : "=r"((r)[0]), "=r"((r)[1]), "=r"((r)[2]), "=r"((r)[3]) : "r"(addr))

#define LDSM4T(r, addr) \
    asm volatile("ldmatrix.sync.aligned.m8n8.x4.trans.shared.b16 {%0,%1,%2,%3}, [%4];" \
        : "=r"((r)[0]), "=r"((r)[1]), "=r"((r)[2]), "=r"((r)[3]) : "r"(addr))

#define MMA16(d, a, b0, b1) \
    asm volatile("mma.sync.aligned.m16n8k16.row.col.f32.f16.f16.f32 " \
        "{%0,%1,%2,%3}, {%4,%5,%6,%7}, {%8,%9}, {%0,%1,%2,%3};" \
        : "+f"((d)[0]), "+f"((d)[1]), "+f"((d)[2]), "+f"((d)[3]) \
        : "r"((a)[0]), "r"((a)[1]), "r"((a)[2]), "r"((a)[3]), \
          "r"(b0), "r"(b1))

#define NBAR(id) asm volatile("bar.sync %0, 256;" :: "r"(id) : "memory")

__device__ __forceinline__ unsigned h2u(float x, float y) {
    __half2 h = __floats2half2_rn(x, y);
    return *(unsigned*)&h;
}

// ---------------------------------------------------------------------------
// weight convert: fp32 -> fp16 buffer, one-time layout
// ---------------------------------------------------------------------------
struct WP {
    const float* wq[3]; const float* wkv[3]; const float* wout[3];
    const float* w1; const float* w2;
};
__global__ __launch_bounds__(256) void wconv_kernel(WP p)
{
    int idx = blockIdx.x * 256 + threadIdx.x;
    if (idx >= 229376) return;
    float v;
    if (idx < 147456) {
        int strip = idx >> 14, rem = idx & 16383;
        int a = strip / 3, r = strip - a * 3;
        v = (r == 0) ? p.wq[a][rem] : p.wkv[a][(r - 1) * 16384 + rem];
    } else if (idx < 196608) {
        int rem = idx - 147456;
        int n = rem / 384, k = rem - n * 384;
        v = p.wout[k >> 7][n * 128 + (k & 127)];
    } else if (idx < 212992) v = p.w1[idx - 196608];
    else                     v = p.w2[idx - 212992];
    g_wh[idx] = __float2half(v);
}

// ---------------------------------------------------------------------------
// prep: xe = 2*x + px + py + pz, transpose (B,C,S) -> (token, C), fp16
// ---------------------------------------------------------------------------
__global__ __launch_bounds__(256) void prep_kernel(
    const float* __restrict__ x,  const float* __restrict__ px,
    const float* __restrict__ py, const float* __restrict__ pz)
{
    __shared__ float tile[64][129];
    int base = blockIdx.x * 64;
    int b    = base / SS;
    int sp0  = base % SS;

    for (int e = threadIdx.x; e < 64 * 128; e += 256) {
        int c = e >> 6;
        int s = e & 63;
        int spatial = sp0 + s;
        int zi = spatial % 48;
        int yi = (spatial / 48) % 48;
        int xi = spatial / 2304;
        tile[s][c] = 2.0f * x[(size_t)b * 128 * SS + (size_t)c * SS + spatial]
                   + px[c * 48 + xi] + py[c * 48 + yi] + pz[c * 48 + zi];
    }
    __syncthreads();
    for (int e = threadIdx.x; e < 64 * 128; e += 256) {
        int s = e >> 7;
        int c = e & 127;
        g_xe[(size_t)(base + s) * 128 + c] = __float2half(tile[s][c]);
    }
}

// ---------------------------------------------------------------------------
// fused QKV + attention v3: grid (288, 3 axes); 512 threads = 2 warp-groups.
// Each group processes 8 interleaved sequences with private A (2x12KB) and
// KV (36KB) buffers; both share the axis weight tile W (96KB). Warp = head:
// warp h computes its head's q/k/v columns; Q stays in registers (C-frag ->
// A-frag repack), K/V go to warp-private smem. Group sync via named barriers.
// ---------------------------------------------------------------------------
#define ATTN3_SMEM 221184
#define EXP2_SCALE 0.36067376022224085f   // 0.25 * log2(e)

__global__ __launch_bounds__(512, 1) void attn3_kernel()
{
    extern __shared__ __align__(16) char smc[];
    unsigned sbase = (unsigned)__cvta_generic_to_shared(smc);
    const unsigned sW = sbase;

    int tid  = threadIdx.x;
    int gid  = tid >> 8;           // warp-group 0/1
    int gtid = tid & 255;
    int lane = tid & 31;
    int h    = (gtid >> 5);        // warp in group = head
    int g    = lane >> 2, t = lane & 3;

    unsigned gA  = sbase + 98304 + (unsigned)gid * 61440;  // 2 x 12288
    unsigned gKV = gA + 24576;                             // 36864 (K,V)
    char*   KVc  = smc + 98304 + gid * 61440 + 24576;
    __half* Os   = (__half*)KVc;                           // aliases KV

    int axis = blockIdx.y;
    int stride = (axis == 0) ? 2304 : (axis == 1 ? 48 : 1);

    // ---- stage W (384 rows x 256B swizzled), all 512 threads ----
    const __half* Wsrc = g_wh + (size_t)axis * 49152;
#pragma unroll
    for (int i = 0; i < 12; i++) {
        int idx = tid + i * 512;
        int row = idx >> 4, seg = idx & 15;
        cpa16_s(sW + row * 256 + (unsigned)((seg * 16) ^ ((row & 7) << 4)),
                Wsrc + (size_t)row * 128 + seg * 8);
    }
    CP_COMMIT();

#define BASE_OF(sq, bs) do {                                                  \
        int b_ = (sq) / 2304, rr_ = (sq) % 2304;                              \
        int o1_ = rr_ / 48, o2_ = rr_ % 48;                                   \
        if (axis == 0)      bs = (long)b_ * SS + o1_ * 48 + o2_;              \
        else if (axis == 1) bs = (long)b_ * SS + o1_ * 2304 + o2_;            \
        else                bs = (long)b_ * SS + o1_ * 2304 + (long)o2_ * 48; \
    } while (0)

#define STAGE_A(bs, buf) do {                                                 \
        _Pragma("unroll")                                                     \
        for (int it_ = 0; it_ < 3; it_++) {                                   \
            int idx_ = gtid + it_ * 256;                                      \
            int row_ = idx_ >> 4, seg_ = idx_ & 15;                           \
            cpa16_s(gA + (buf) * 12288 + row_ * 256                           \
                    + (unsigned)((seg_ * 16) ^ ((row_ & 7) << 4)),            \
                    g_xe + (size_t)((bs) + (long)row_ * stride) * 128         \
                    + seg_ * 8);                                              \
        }                                                                     \
    } while (0)

    int seqbase = blockIdx.x * 16 + gid;     // group's seqs: +2 per step
    { long bs0; BASE_OF(seqbase, bs0); STAGE_A(bs0, 0); }
    CP_COMMIT();
    CP_WAIT1();          // W complete (A0 still in flight)
    __syncthreads();     // W visible CTA-wide

    // fragment addressing constants
    unsigned hiA = (unsigned)((lane >> 4) << 4);
    unsigned xA  = (unsigned)((lane & 7) << 4);
    int raL  = lane & 15;
    int rbL  = ((lane & 16) >> 1) + (lane & 7);
    unsigned hiB = (unsigned)(((lane >> 3) & 1) << 4);
    unsigned xB  = (unsigned)((lane & 7) << 4);
    int barid = gid + 1;

    for (int i = 0; i < 8; i++) {
        long bs; BASE_OF(seqbase + 2 * i, bs);
        if (i + 1 < 8) {
            long bn; BASE_OF(seqbase + 2 * (i + 1), bn);
            STAGE_A(bn, (i + 1) & 1);
            CP_COMMIT(); CP_WAIT1();
        } else {
            CP_WAIT0();
        }
        NBAR(barid);     // A(i) visible group-wide; prior seq fully done

        // ---- GEMM: warp computes its head's q|k|v (48 cols), M=48, K=128 --
        unsigned sAc = gA + (unsigned)((i & 1) * 12288);
        float acc[3][6][4];
#pragma unroll
        for (int mt = 0; mt < 3; mt++)
#pragma unroll
            for (int nt = 0; nt < 6; nt++)
#pragma unroll
                for (int q = 0; q < 4; q++) acc[mt][nt][q] = 0.f;

#pragma unroll
        for (int kt = 0; kt < 8; kt++) {
            unsigned a[3][4];
#pragma unroll
            for (int mt = 0; mt < 3; mt++)
                LDSM4(a[mt], sAc + (unsigned)((mt * 16 + raL) * 256)
                             + (((unsigned)(kt * 32) + hiA) ^ xA));
#pragma unroll
            for (int np = 0; np < 3; np++) {
                int rowb = np * 128 + h * 16 + rbL;
                unsigned b[4];
                LDSM4(b, sW + (unsigned)(rowb * 256)
                         + (((unsigned)(kt * 32) + hiB) ^ xB));
#pragma unroll
                for (int mt = 0; mt < 3; mt++) {
                    MMA16(acc[mt][2 * np],     a[mt], b[0], b[1]);
                    MMA16(acc[mt][2 * np + 1], a[mt], b[2], b[3]);
                }
            }
        }

        // ---- Q: C-frag -> A-frag repack (registers only) ----
        unsigned qf[3][4];
#pragma unroll
        for (int mt = 0; mt < 3; mt++) {
            qf[mt][0] = h2u(acc[mt][0][0], acc[mt][0][1]);
            qf[mt][1] = h2u(acc[mt][0][2], acc[mt][0][3]);
            qf[mt][2] = h2u(acc[mt][1][0], acc[mt][1][1]);
            qf[mt][3] = h2u(acc[mt][1][2], acc[mt][1][3]);
        }
        // ---- K,V -> warp-private smem (48B rows) ----
#pragma unroll
        for (int np = 1; np < 3; np++)
#pragma unroll
            for (int nts = 0; nts < 2; nts++) {
                int nt = np * 2 + nts;
                char* dst = KVc + (np - 1) * 18432 + h * 2304
                          + (nts * 8 + 2 * t) * 2;
#pragma unroll
                for (int mt = 0; mt < 3; mt++) {
                    int r0 = mt * 16 + g;
                    *(__half2*)(dst + r0 * 48) =
                        __floats2half2_rn(acc[mt][nt][0], acc[mt][nt][1]);
                    *(__half2*)(dst + (r0 + 8) * 48) =
                        __floats2half2_rn(acc[mt][nt][2], acc[mt][nt][3]);
                }
            }
        __syncwarp();

        // ---- scores S = Q @ K^T ----
        unsigned Kb = gKV + (unsigned)(h * 2304);
        unsigned Vb = Kb + 18432u;
        float s[3][6][4];
#pragma unroll
        for (int mt = 0; mt < 3; mt++)
#pragma unroll
            for (int nt = 0; nt < 6; nt++)
#pragma unroll
                for (int q = 0; q < 4; q++) s[mt][nt][q] = 0.f;
#pragma unroll
        for (int nt2 = 0; nt2 < 3; nt2++) {
            unsigned bb[4];
            LDSM4(bb, Kb + (unsigned)((nt2 * 16 + rbL) * 48) + hiB);
#pragma unroll
            for (int mt = 0; mt < 3; mt++) {
                MMA16(s[mt][2 * nt2],     qf[mt], bb[0], bb[1]);
                MMA16(s[mt][2 * nt2 + 1], qf[mt], bb[2], bb[3]);
            }
        }

        // ---- max-free softmax, norm deferred to O ----
        float inv[3][2];
#pragma unroll
        for (int mt = 0; mt < 3; mt++)
#pragma unroll
            for (int hi = 0; hi < 2; hi++) {
                float sum = 0.f;
#pragma unroll
                for (int nt = 0; nt < 6; nt++)
#pragma unroll
                    for (int lo = 0; lo < 2; lo++) {
                        float e = exp2f(s[mt][nt][hi * 2 + lo] * EXP2_SCALE);
                        s[mt][nt][hi * 2 + lo] = e;
                        sum += e;
                    }
                sum += __shfl_xor_sync(0xffffffffu, sum, 1);
                sum += __shfl_xor_sync(0xffffffffu, sum, 2);
                inv[mt][hi] = 1.f / sum;
            }

        // ---- O = P_unnorm @ V ----
        float o[3][2][4];
#pragma unroll
        for (int mt = 0; mt < 3; mt++)
#pragma unroll
            for (int nt = 0; nt < 2; nt++)
#pragma unroll
                for (int q = 0; q < 4; q++) o[mt][nt][q] = 0.f;
#pragma unroll
        for (int kt = 0; kt < 3; kt++) {
            unsigned vb[4];
            LDSM4T(vb, Vb + (unsigned)((kt * 16 + raL) * 48) + hiA);
            unsigned pa[3][4];
#pragma unroll
            for (int mt = 0; mt < 3; mt++) {
                pa[mt][0] = h2u(s[mt][2 * kt][0],     s[mt][2 * kt][1]);
                pa[mt][1] = h2u(s[mt][2 * kt][2],     s[mt][2 * kt][3]);
                pa[mt][2] = h2u(s[mt][2 * kt + 1][0], s[mt][2 * kt + 1][1]);
                pa[mt][3] = h2u(s[mt][2 * kt + 1][2], s[mt][2 * kt + 1][3]);
            }
#pragma unroll
            for (int mt = 0; mt < 3; mt++) {
                MMA16(o[mt][0], pa[mt], vb[0], vb[1]);
                MMA16(o[mt][1], pa[mt], vb[2], vb[3]);
            }
        }

        NBAR(barid);   // all group warps done reading K/V (Os aliases KV)

        // ---- normalize O, stage, coalesced group store ----
#pragma unroll
        for (int mt = 0; mt < 3; mt++)
#pragma unroll
            for (int nt = 0; nt < 2; nt++) {
                int col = h * 16 + nt * 8 + 2 * t;
                int r0 = mt * 16 + g;
                *(__half2*)(Os + r0 * 136 + col) =
                    __floats2half2_rn(o[mt][nt][0] * inv[mt][0],
                                      o[mt][nt][1] * inv[mt][0]);
                *(__half2*)(Os + (r0 + 8) * 136 + col) =
                    __floats2half2_rn(o[mt][nt][2] * inv[mt][1],
                                      o[mt][nt][3] * inv[mt][1]);
            }
        NBAR(barid);

#pragma unroll
        for (int it = 0; it < 3; it++) {
            int idx = gtid + it * 256;
            int row = idx >> 4, c = idx & 15;
            *(uint4*)(g_o + (size_t)(bs + (long)row * stride) * 384
                      + axis * 128 + c * 8) = *(const uint4*)(Os + row * 136 + c * 8);
        }
    }
#undef BASE_OF
#undef STAGE_A
}

// ---------------------------------------------------------------------------
// fused tail: outproj(+bias3+res(g_xe)) -> LN1 -> mlp1(relu) -> mlp2(+res)
// -> LN2 -> transposed fp32 store. Intermediates never touch DRAM.
// ---------------------------------------------------------------------------
#define FUSE_SMEM 100864

struct FP {
    const float *bo0, *bo1, *bo2, *b1, *b2, *lng, *lnb;
    float* out;
};

__global__ __launch_bounds__(256, 2) void fuse_kernel(FP p)
{
    extern __shared__ __align__(16) char smc[];
    unsigned sR = (unsigned)__cvta_generic_to_shared(smc);
    unsigned sX = sR + 68096;
    float* Ct = (float*)smc;

    int tid = threadIdx.x, w = tid >> 5, lane = tid & 31;
    int mw = w & 3, nw = w >> 2;
    int g = lane >> 2, t = lane & 3;
    long m0 = (long)blockIdx.x * 128;

    int rowA  = mw * 32 + (lane & 15);
    int rowB0 = nw * 64 + ((lane & 16) >> 1) + (lane & 7);
    unsigned hiA = (unsigned)((lane >> 4) << 4);
    unsigned hiB = (unsigned)(((lane >> 3) & 1) << 4);
    unsigned xA = (unsigned)((rowA & 7) << 4);
    unsigned xB = (unsigned)((rowB0 & 7) << 4);

    // ================= P1: outproj, A=g_o (lda 384), B=wout_cat, K=384 ======
    float acc[2][8][4];
#pragma unroll
    for (int mt = 0; mt < 2; mt++)
#pragma unroll
        for (int nt = 0; nt < 8; nt++)
#pragma unroll
            for (int i = 0; i < 4; i++) acc[mt][nt][i] = 0.f;
    {
        unsigned sA = sR, sB = sR + 32768;
        const __half* Ap = g_o;
        const __half* Bp = g_wh + 147456;

#define STAGE1(c, buf) do {                                                   \
        int k0_ = (c) * 64;                                                   \
        _Pragma("unroll")                                                     \
        for (int i_ = 0; i_ < 4; i_++) {                                      \
            int idx_ = tid + 256 * i_;                                        \
            int row_ = idx_ >> 3, seg_ = idx_ & 7;                            \
            unsigned dcol_ = (unsigned)((seg_ * 16) ^ ((row_ & 7) << 4));     \
            cpa16_s(sA + (buf) * 16384 + row_ * 128 + dcol_,                  \
                    Ap + (m0 + row_) * 384 + k0_ + seg_ * 8);                 \
            cpa16_s(sB + (buf) * 16384 + row_ * 128 + dcol_,                  \
                    Bp + (size_t)row_ * 384 + k0_ + seg_ * 8);                \
        }                                                                     \
    } while (0)

        STAGE1(0, 0); CP_COMMIT();
        for (int c = 0; c < 6; c++) {
            if (c + 1 < 6) { STAGE1(c + 1, (c + 1) & 1); CP_COMMIT(); CP_WAIT1(); }
            else           { CP_WAIT0(); }
            __syncthreads();
            unsigned baseA = sA + (c & 1) * 16384;
            unsigned baseB = sB + (c & 1) * 16384;
#pragma unroll
            for (int kt = 0; kt < 4; kt++) {
                unsigned a[2][4];
#pragma unroll
                for (int mt = 0; mt < 2; mt++)
                    LDSM4(a[mt], baseA + (rowA + mt * 16) * 128
                                 + (((unsigned)(kt * 32) + hiA) ^ xA));
#pragma unroll
                for (int np = 0; np < 4; np++) {
                    unsigned b[4];
                    LDSM4(b, baseB + (rowB0 + np * 16) * 128
                             + (((unsigned)(kt * 32) + hiB) ^ xB));
                    MMA16(acc[0][2 * np],     a[0], b[0], b[1]);
                    MMA16(acc[1][2 * np],     a[1], b[0], b[1]);
                    MMA16(acc[0][2 * np + 1], a[0], b[2], b[3]);
                    MMA16(acc[1][2 * np + 1], a[1], b[2], b[3]);
                }
            }
            __syncthreads();
        }
#undef STAGE1
    }

    // epilogue P1: Ct = acc + (bo0+bo1+bo2) + g_xe residual
#pragma unroll
    for (int mt = 0; mt < 2; mt++)
#pragma unroll
        for (int nt = 0; nt < 8; nt++) {
            int rl = mw * 32 + mt * 16 + g;
            int cc = nw * 64 + nt * 8 + 2 * t;
            size_t tok = m0 + rl;
            float b0 = p.bo0[cc] + p.bo1[cc] + p.bo2[cc];
            float b1v = p.bo0[cc + 1] + p.bo1[cc + 1] + p.bo2[cc + 1];
            Ct[rl * 133 + cc]     = acc[mt][nt][0] + b0 + __half2float(g_xe[tok * 128 + cc]);
            Ct[rl * 133 + cc + 1] = acc[mt][nt][1] + b1v + __half2float(g_xe[tok * 128 + cc + 1]);
            Ct[(rl + 8) * 133 + cc]     = acc[mt][nt][2] + b0 + __half2float(g_xe[(tok + 8) * 128 + cc]);
            Ct[(rl + 8) * 133 + cc + 1] = acc[mt][nt][3] + b1v + __half2float(g_xe[(tok + 8) * 128 + cc + 1]);
        }
    __syncthreads();

    // LN1 -> xln (fp16 swizzled tile, row stride 256B)
    for (int r = w; r < 128; r += 8) {
        float v[4], s = 0.f, s2 = 0.f;
#pragma unroll
        for (int k = 0; k < 4; k++) {
            v[k] = Ct[r * 133 + lane + 32 * k];
            s += v[k]; s2 += v[k] * v[k];
        }
        for (int off = 16; off; off >>= 1) {
            s  += __shfl_xor_sync(0xffffffffu, s,  off);
            s2 += __shfl_xor_sync(0xffffffffu, s2, off);
        }
        float m   = s * (1.f / 128.f);
        float var = s2 * (1.f / 128.f) - m * m;
        float rs  = rsqrtf(var + 1e-5f);
        unsigned rxor = (unsigned)((r & 7) << 4);
#pragma unroll
        for (int k = 0; k < 4; k++) {
            int cc = lane + 32 * k;
            float y = (v[k] - m) * rs * p.lng[cc] + p.lnb[cc];
            *(__half*)(smc + 68096 + r * 256 + ((unsigned)(2 * cc) ^ rxor)) =
                __float2half(y);
        }
    }
    __syncthreads();

    // ================= stage w1 -> R1[0,32K), w2 -> R1[32K,64K) =============
    {
        const __half* w1p = g_wh + 196608;
        const __half* w2p = g_wh + 212992;
#pragma unroll
        for (int i = 0; i < 8; i++) {
            int idx = tid + i * 256;
            int row = idx >> 4, seg = idx & 15;
            unsigned dcol = (unsigned)((seg * 16) ^ ((row & 7) << 4));
            cpa16_s(sR + row * 256 + dcol, w1p + row * 128 + seg * 8);
            cpa16_s(sR + 32768 + row * 256 + dcol, w2p + row * 128 + seg * 8);
        }
        CP_COMMIT(); CP_WAIT0();
        __syncthreads();
    }

    // ================= P2: h = relu(xln @ w1^T + b1), K=128 =================
    float acc2[2][8][4];
#pragma unroll
    for (int mt = 0; mt < 2; mt++)
#pragma unroll
        for (int nt = 0; nt < 8; nt++)
#pragma unroll
            for (int i = 0; i < 4; i++) acc2[mt][nt][i] = 0.f;

#pragma unroll
    for (int kt = 0; kt < 8; kt++) {
        unsigned a[2][4];
#pragma unroll
        for (int mt = 0; mt < 2; mt++)
            LDSM4(a[mt], sX + (rowA + mt * 16) * 256
                         + (((unsigned)(kt * 32) + hiA) ^ xA));
#pragma unroll
        for (int np = 0; np < 4; np++) {
            unsigned b[4];
            LDSM4(b, sR + (rowB0 + np * 16) * 256
                     + (((unsigned)(kt * 32) + hiB) ^ xB));
            MMA16(acc2[0][2 * np],     a[0], b[0], b[1]);
            MMA16(acc2[1][2 * np],     a[1], b[0], b[1]);
            MMA16(acc2[0][2 * np + 1], a[0], b[2], b[3]);
            MMA16(acc2[1][2 * np + 1], a[1], b[2], b[3]);
        }
    }
    __syncthreads();

    // h tile (fp16 swizzled, row 256B) at R1[0,32K)
#pragma unroll
    for (int mt = 0; mt < 2; mt++)
#pragma unroll
        for (int nt = 0; nt < 8; nt++) {
            int rl = mw * 32 + mt * 16 + g;
            int cc = nw * 64 + nt * 8 + 2 * t;
            float b0 = p.b1[cc], b1v = p.b1[cc + 1];
            unsigned c2 = (unsigned)(2 * cc);
            *(__half2*)(smc + rl * 256 + (c2 ^ (unsigned)((rl & 7) << 4))) =
                __floats2half2_rn(fmaxf(acc2[mt][nt][0] + b0, 0.f),
                                  fmaxf(acc2[mt][nt][1] + b1v, 0.f));
            *(__half2*)(smc + (rl + 8) * 256 + (c2 ^ (unsigned)(((rl + 8) & 7) << 4))) =
                __floats2half2_rn(fmaxf(acc2[mt][nt][2] + b0, 0.f),
                                  fmaxf(acc2[mt][nt][3] + b1v, 0.f));
        }
    __syncthreads();

    // ================= P3: y = h @ w2^T + b2 + xln, K=128 ===================
    float acc3[2][8][4];
#pragma unroll
    for (int mt = 0; mt < 2; mt++)
#pragma unroll
        for (int nt = 0; nt < 8; nt++)
#pragma unroll
            for (int i = 0; i < 4; i++) acc3[mt][nt][i] = 0.f;

#pragma unroll
    for (int kt = 0; kt < 8; kt++) {
        unsigned a[2][4];
#pragma unroll
        for (int mt = 0; mt < 2; mt++)
            LDSM4(a[mt], sR + (rowA + mt * 16) * 256
                         + (((unsigned)(kt * 32) + hiA) ^ xA));
#pragma unroll
        for (int np = 0; np < 4; np++) {
            unsigned b[4];
            LDSM4(b, sR + 32768 + (rowB0 + np * 16) * 256
                     + (((unsigned)(kt * 32) + hiB) ^ xB));
            MMA16(acc3[0][2 * np],     a[0], b[0], b[1]);
            MMA16(acc3[1][2 * np],     a[1], b[0], b[1]);
            MMA16(acc3[0][2 * np + 1], a[0], b[2], b[3]);
            MMA16(acc3[1][2 * np + 1], a[1], b[2], b[3]);
        }
    }
    __syncthreads();

    // epilogue P3: Ct = acc3 + b2 + xln residual
#pragma unroll
    for (int mt = 0; mt < 2; mt++)
#pragma unroll
        for (int nt = 0; nt < 8; nt++) {
            int rl = mw * 32 + mt * 16 + g;
            int cc = nw * 64 + nt * 8 + 2 * t;
            float b0 = p.b2[cc], b1v = p.b2[cc + 1];
            unsigned c2 = (unsigned)(2 * cc);
            __half2 r0 = *(const __half2*)(smc + 68096 + rl * 256
                                           + (c2 ^ (unsigned)((rl & 7) << 4)));
            __half2 r1 = *(const __half2*)(smc + 68096 + (rl + 8) * 256
                                           + (c2 ^ (unsigned)(((rl + 8) & 7) << 4)));
            float2 f0 = __half22float2(r0);
            float2 f1 = __half22float2(r1);
            Ct[rl * 133 + cc]           = acc3[mt][nt][0] + b0 + f0.x;
            Ct[rl * 133 + cc + 1]       = acc3[mt][nt][1] + b1v + f0.y;
            Ct[(rl + 8) * 133 + cc]     = acc3[mt][nt][2] + b0 + f1.x;
            Ct[(rl + 8) * 133 + cc + 1] = acc3[mt][nt][3] + b1v + f1.y;
        }
    __syncthreads();

    // LN2 (in place in Ct)
    for (int r = w; r < 128; r += 8) {
        float v[4], s = 0.f, s2 = 0.f;
#pragma unroll
        for (int k = 0; k < 4; k++) {
            v[k] = Ct[r * 133 + lane + 32 * k];
            s += v[k]; s2 += v[k] * v[k];
        }
        for (int off = 16; off; off >>= 1) {
            s  += __shfl_xor_sync(0xffffffffu, s,  off);
            s2 += __shfl_xor_sync(0xffffffffu, s2, off);
        }
        float m   = s * (1.f / 128.f);
        float var = s2 * (1.f / 128.f) - m * m;
        float rs  = rsqrtf(var + 1e-5f);
#pragma unroll
        for (int k = 0; k < 4; k++) {
            int cc = lane + 32 * k;
            Ct[r * 133 + cc] = (v[k] - m) * rs * p.lng[cc] + p.lnb[cc];
        }
    }
    __syncthreads();

    // transposed fp32 store to (B,C,X,Y,Z)
    int  bi  = (int)(m0 / SS);
    long sp0 = m0 % SS;
    float* outp = p.out + (size_t)bi * 128 * SS + sp0;
    for (int e = tid; e < 128 * 128; e += 256) {
        int cc = e >> 7, ss = e & 127;
        outp[(size_t)cc * SS + ss] = Ct[ss * 133 + cc];
    }
}

// ---------------------------------------------------------------------------
// launch
// ---------------------------------------------------------------------------
extern "C" void kernel_launch(void* const* d_in, const int* in_sizes, int n_in,
                              void* d_out, int out_size)
{
    (void)in_sizes; (void)n_in; (void)out_size;
    const float* x    = (const float*)d_in[0];
    const float* px   = (const float*)d_in[1];
    const float* py   = (const float*)d_in[2];
    const float* pz   = (const float*)d_in[3];

    cudaFuncSetAttribute((const void*)attn3_kernel,
                         cudaFuncAttributeMaxDynamicSharedMemorySize, ATTN3_SMEM);
    cudaFuncSetAttribute((const void*)fuse_kernel,
                         cudaFuncAttributeMaxDynamicSharedMemorySize, FUSE_SMEM);

    WP wp;
    for (int a = 0; a < 3; a++) {
        wp.wq[a]   = (const float*)d_in[4 + 4 * a];
        wp.wkv[a]  = (const float*)d_in[5 + 4 * a];
        wp.wout[a] = (const float*)d_in[6 + 4 * a];
    }
    wp.w1 = (const float*)d_in[18];
    wp.w2 = (const float*)d_in[20];
    wconv_kernel<<<896, 256>>>(wp);

    prep_kernel<<<NT / 64, 256>>>(x, px, py, pz);

    attn3_kernel<<<dim3(288, 3), 512, ATTN3_SMEM>>>();

    FP fp;
    fp.bo0 = (const float*)d_in[7];
    fp.bo1 = (const float*)d_in[11];
    fp.bo2 = (const float*)d_in[15];
    fp.b1  = (const float*)d_in[19];
    fp.b2  = (const float*)d_in[21];
    fp.lng = (const float*)d_in[16];
    fp.lnb = (const float*)d_in[17];
    fp.out = (float*)d_out;
    fuse_kernel<<<NT / 128, 256, FUSE_SMEM>>>(fp);
}

// round 11
// speedup vs baseline: 1.0011x; 1.0011x over previous
#include <cuda_runtime.h>
#include <cuda_fp16.h>

// Problem constants
#define SS   110592          // 48^3
#define NT   221184          // NB*SS tokens

// Scratch (device globals; no allocation allowed) — all intermediates fp16
__device__ __half g_xe [NT * 128];            // pos-embedded input (residual 1)
__device__ __half g_o  [(size_t)NT * 384];    // attention outputs, 3 axes
// fp16 weights: [0,147456) qkv blocks (3 axes x [384][128]), [147456,196608)
// wout_cat (128 rows x 384), [196608,212992) w1, [212992,229376) w2
__device__ __half g_wh [229376];

// ---------------------------------------------------------------------------
// helpers
// ---------------------------------------------------------------------------
__device__ __forceinline__ void cpa16_s(unsigned d, const void* s) {
    asm volatile("cp.async.cg.shared.global [%0], [%1], 16;" :: "r"(d), "l"(s));
}
#define CP_COMMIT() asm volatile("cp.async.commit_group;")
#define CP_WAIT1()  asm volatile("cp.async.wait_group 1;")
#define CP_WAIT0()  asm volatile("cp.async.wait_group 0;")

#define LDSM4(r, addr) \
    asm volatile("ldmatrix.sync.aligned.m8n8.x4.shared.b16 {%0,%1,%2,%3}, [%4];" \
        : "=r"((r)[0]), "=r"((r)[1]), "=r"((r)[2]), "=r"((r)[3]) : "r"(addr))

#define LDSM4T(r, addr) \
    asm volatile("ldmatrix.sync.aligned.m8n8.x4.trans.shared.b16 {%0,%1,%2,%3}, [%4];" \
        : "=r"((r)[0]), "=r"((r)[1]), "=r"((r)[2]), "=r"((r)[3]) : "r"(addr))

#define MMA16(d, a, b0, b1) \
    asm volatile("mma.sync.aligned.m16n8k16.row.col.f32.f16.f16.f32 " \
        "{%0,%1,%2,%3}, {%4,%5,%6,%7}, {%8,%9}, {%0,%1,%2,%3};" \
        : "+f"((d)[0]), "+f"((d)[1]), "+f"((d)[2]), "+f"((d)[3]) \
        : "r"((a)[0]), "r"((a)[1]), "r"((a)[2]), "r"((a)[3]), \
          "r"(b0), "r"(b1))

#define NBAR(id) asm volatile("bar.sync %0, 256;" :: "r"(id) : "memory")

__device__ __forceinline__ unsigned h2u(float x, float y) {
    __half2 h = __floats2half2_rn(x, y);
    return *(unsigned*)&h;
}

// ---------------------------------------------------------------------------
// weight convert: fp32 -> fp16 buffer, one-time layout
// ---------------------------------------------------------------------------
struct WP {
    const float* wq[3]; const float* wkv[3]; const float* wout[3];
    const float* w1; const float* w2;
};
__global__ __launch_bounds__(256) void wconv_kernel(WP p)
{
    int idx = blockIdx.x * 256 + threadIdx.x;
    if (idx >= 229376) return;
    float v;
    if (idx < 147456) {
        int strip = idx >> 14, rem = idx & 16383;
        int a = strip / 3, r = strip - a * 3;
        v = (r == 0) ? p.wq[a][rem] : p.wkv[a][(r - 1) * 16384 + rem];
    } else if (idx < 196608) {
        int rem = idx - 147456;
        int n = rem / 384, k = rem - n * 384;
        v = p.wout[k >> 7][n * 128 + (k & 127)];
    } else if (idx < 212992) v = p.w1[idx - 196608];
    else                     v = p.w2[idx - 212992];
    g_wh[idx] = __float2half(v);
}

// ---------------------------------------------------------------------------
// prep: xe = 2*x + px + py + pz, transpose (B,C,S) -> (token, C), fp16
// ---------------------------------------------------------------------------
__global__ __launch_bounds__(256) void prep_kernel(
    const float* __restrict__ x,  const float* __restrict__ px,
    const float* __restrict__ py, const float* __restrict__ pz)
{
    __shared__ float tile[64][129];
    int base = blockIdx.x * 64;
    int b    = base / SS;
    int sp0  = base % SS;

    for (int e = threadIdx.x; e < 64 * 128; e += 256) {
        int c = e >> 6;
        int s = e & 63;
        int spatial = sp0 + s;
        int zi = spatial % 48;
        int yi = (spatial / 48) % 48;
        int xi = spatial / 2304;
        tile[s][c] = 2.0f * x[(size_t)b * 128 * SS + (size_t)c * SS + spatial]
                   + px[c * 48 + xi] + py[c * 48 + yi] + pz[c * 48 + zi];
    }
    __syncthreads();
    for (int e = threadIdx.x; e < 64 * 128; e += 256) {
        int s = e >> 7;
        int c = e & 127;
        g_xe[(size_t)(base + s) * 128 + c] = __float2half(tile[s][c]);
    }
}

// ---------------------------------------------------------------------------
// fused QKV + attention v3: grid (288, 3 axes); 512 threads = 2 warp-groups.
// Each group processes 8 interleaved sequences with private A (2x12KB) and
// KV (36KB) buffers; both share the axis weight tile W (96KB). Warp = head:
// warp h computes its head's q/k/v columns; Q stays in registers (C-frag ->
// A-frag repack), K/V go to warp-private smem. Group sync via named barriers.
// ---------------------------------------------------------------------------
#define ATTN3_SMEM 221184
#define EXP2_SCALE 0.36067376022224085f   // 0.25 * log2(e)

__global__ __launch_bounds__(512, 1) void attn3_kernel()
{
    extern __shared__ __align__(16) char smc[];
    unsigned sbase = (unsigned)__cvta_generic_to_shared(smc);
    const unsigned sW = sbase;

    int tid  = threadIdx.x;
    int gid  = tid >> 8;           // warp-group 0/1
    int gtid = tid & 255;
    int lane = tid & 31;
    int h    = (gtid >> 5);        // warp in group = head
    int g    = lane >> 2, t = lane & 3;

    unsigned gA  = sbase + 98304 + (unsigned)gid * 61440;  // 2 x 12288
    unsigned gKV = gA + 24576;                             // 36864 (K,V)
    char*   KVc  = smc + 98304 + gid * 61440 + 24576;
    __half* Os   = (__half*)KVc;                           // aliases KV

    int axis = blockIdx.y;
    int stride = (axis == 0) ? 2304 : (axis == 1 ? 48 : 1);

    // ---- stage W (384 rows x 256B swizzled), all 512 threads ----
    const __half* Wsrc = g_wh + (size_t)axis * 49152;
#pragma unroll
    for (int i = 0; i < 12; i++) {
        int idx = tid + i * 512;
        int row = idx >> 4, seg = idx & 15;
        cpa16_s(sW + row * 256 + (unsigned)((seg * 16) ^ ((row & 7) << 4)),
                Wsrc + (size_t)row * 128 + seg * 8);
    }
    CP_COMMIT();

#define BASE_OF(sq, bs) do {                                                  \
        int b_ = (sq) / 2304, rr_ = (sq) % 2304;                              \
        int o1_ = rr_ / 48, o2_ = rr_ % 48;                                   \
        if (axis == 0)      bs = (long)b_ * SS + o1_ * 48 + o2_;              \
        else if (axis == 1) bs = (long)b_ * SS + o1_ * 2304 + o2_;            \
        else                bs = (long)b_ * SS + o1_ * 2304 + (long)o2_ * 48; \
    } while (0)

#define STAGE_A(bs, buf) do {                                                 \
        _Pragma("unroll")                                                     \
        for (int it_ = 0; it_ < 3; it_++) {                                   \
            int idx_ = gtid + it_ * 256;                                      \
            int row_ = idx_ >> 4, seg_ = idx_ & 15;                           \
            cpa16_s(gA + (buf) * 12288 + row_ * 256                           \
                    + (unsigned)((seg_ * 16) ^ ((row_ & 7) << 4)),            \
                    g_xe + (size_t)((bs) + (long)row_ * stride) * 128         \
                    + seg_ * 8);                                              \
        }                                                                     \
    } while (0)

    int seqbase = blockIdx.x * 16 + gid;     // group's seqs: +2 per step
    { long bs0; BASE_OF(seqbase, bs0); STAGE_A(bs0, 0); }
    CP_COMMIT();
    CP_WAIT1();          // W complete (A0 still in flight)
    __syncthreads();     // W visible CTA-wide

    // fragment addressing constants
    unsigned hiA = (unsigned)((lane >> 4) << 4);
    unsigned xA  = (unsigned)((lane & 7) << 4);
    int raL  = lane & 15;
    int rbL  = ((lane & 16) >> 1) + (lane & 7);
    unsigned hiB = (unsigned)(((lane >> 3) & 1) << 4);
    unsigned xB  = (unsigned)((lane & 7) << 4);
    int barid = gid + 1;

    for (int i = 0; i < 8; i++) {
        long bs; BASE_OF(seqbase + 2 * i, bs);
        if (i + 1 < 8) {
            long bn; BASE_OF(seqbase + 2 * (i + 1), bn);
            STAGE_A(bn, (i + 1) & 1);
            CP_COMMIT(); CP_WAIT1();
        } else {
            CP_WAIT0();
        }
        NBAR(barid);     // A(i) visible group-wide; prior seq fully done

        // ---- GEMM: warp computes its head's q|k|v (48 cols), M=48, K=128 --
        unsigned sAc = gA + (unsigned)((i & 1) * 12288);
        float acc[3][6][4];
#pragma unroll
        for (int mt = 0; mt < 3; mt++)
#pragma unroll
            for (int nt = 0; nt < 6; nt++)
#pragma unroll
                for (int q = 0; q < 4; q++) acc[mt][nt][q] = 0.f;

#pragma unroll
        for (int kt = 0; kt < 8; kt++) {
            unsigned a[3][4];
#pragma unroll
            for (int mt = 0; mt < 3; mt++)
                LDSM4(a[mt], sAc + (unsigned)((mt * 16 + raL) * 256)
                             + (((unsigned)(kt * 32) + hiA) ^ xA));
#pragma unroll
            for (int np = 0; np < 3; np++) {
                int rowb = np * 128 + h * 16 + rbL;
                unsigned b[4];
                LDSM4(b, sW + (unsigned)(rowb * 256)
                         + (((unsigned)(kt * 32) + hiB) ^ xB));
#pragma unroll
                for (int mt = 0; mt < 3; mt++) {
                    MMA16(acc[mt][2 * np],     a[mt], b[0], b[1]);
                    MMA16(acc[mt][2 * np + 1], a[mt], b[2], b[3]);
                }
            }
        }

        // ---- Q: C-frag -> A-frag repack (registers only) ----
        unsigned qf[3][4];
#pragma unroll
        for (int mt = 0; mt < 3; mt++) {
            qf[mt][0] = h2u(acc[mt][0][0], acc[mt][0][1]);
            qf[mt][1] = h2u(acc[mt][0][2], acc[mt][0][3]);
            qf[mt][2] = h2u(acc[mt][1][0], acc[mt][1][1]);
            qf[mt][3] = h2u(acc[mt][1][2], acc[mt][1][3]);
        }
        // ---- K,V -> warp-private smem (48B rows) ----
#pragma unroll
        for (int np = 1; np < 3; np++)
#pragma unroll
            for (int nts = 0; nts < 2; nts++) {
                int nt = np * 2 + nts;
                char* dst = KVc + (np - 1) * 18432 + h * 2304
                          + (nts * 8 + 2 * t) * 2;
#pragma unroll
                for (int mt = 0; mt < 3; mt++) {
                    int r0 = mt * 16 + g;
                    *(__half2*)(dst + r0 * 48) =
                        __floats2half2_rn(acc[mt][nt][0], acc[mt][nt][1]);
                    *(__half2*)(dst + (r0 + 8) * 48) =
                        __floats2half2_rn(acc[mt][nt][2], acc[mt][nt][3]);
                }
            }
        __syncwarp();

        // ---- scores S = Q @ K^T ----
        unsigned Kb = gKV + (unsigned)(h * 2304);
        unsigned Vb = Kb + 18432u;
        float s[3][6][4];
#pragma unroll
        for (int mt = 0; mt < 3; mt++)
#pragma unroll
            for (int nt = 0; nt < 6; nt++)
#pragma unroll
                for (int q = 0; q < 4; q++) s[mt][nt][q] = 0.f;
#pragma unroll
        for (int nt2 = 0; nt2 < 3; nt2++) {
            unsigned bb[4];
            LDSM4(bb, Kb + (unsigned)((nt2 * 16 + rbL) * 48) + hiB);
#pragma unroll
            for (int mt = 0; mt < 3; mt++) {
                MMA16(s[mt][2 * nt2],     qf[mt], bb[0], bb[1]);
                MMA16(s[mt][2 * nt2 + 1], qf[mt], bb[2], bb[3]);
            }
        }

        // ---- max-free softmax, norm deferred to O ----
        float inv[3][2];
#pragma unroll
        for (int mt = 0; mt < 3; mt++)
#pragma unroll
            for (int hi = 0; hi < 2; hi++) {
                float sum = 0.f;
#pragma unroll
                for (int nt = 0; nt < 6; nt++)
#pragma unroll
                    for (int lo = 0; lo < 2; lo++) {
                        float e = exp2f(s[mt][nt][hi * 2 + lo] * EXP2_SCALE);
                        s[mt][nt][hi * 2 + lo] = e;
                        sum += e;
                    }
                sum += __shfl_xor_sync(0xffffffffu, sum, 1);
                sum += __shfl_xor_sync(0xffffffffu, sum, 2);
                inv[mt][hi] = 1.f / sum;
            }

        // ---- O = P_unnorm @ V ----
        float o[3][2][4];
#pragma unroll
        for (int mt = 0; mt < 3; mt++)
#pragma unroll
            for (int nt = 0; nt < 2; nt++)
#pragma unroll
                for (int q = 0; q < 4; q++) o[mt][nt][q] = 0.f;
#pragma unroll
        for (int kt = 0; kt < 3; kt++) {
            unsigned vb[4];
            LDSM4T(vb, Vb + (unsigned)((kt * 16 + raL) * 48) + hiA);
            unsigned pa[3][4];
#pragma unroll
            for (int mt = 0; mt < 3; mt++) {
                pa[mt][0] = h2u(s[mt][2 * kt][0],     s[mt][2 * kt][1]);
                pa[mt][1] = h2u(s[mt][2 * kt][2],     s[mt][2 * kt][3]);
                pa[mt][2] = h2u(s[mt][2 * kt + 1][0], s[mt][2 * kt + 1][1]);
                pa[mt][3] = h2u(s[mt][2 * kt + 1][2], s[mt][2 * kt + 1][3]);
            }
#pragma unroll
            for (int mt = 0; mt < 3; mt++) {
                MMA16(o[mt][0], pa[mt], vb[0], vb[1]);
                MMA16(o[mt][1], pa[mt], vb[2], vb[3]);
            }
        }

        NBAR(barid);   // all group warps done reading K/V (Os aliases KV)

        // ---- normalize O, stage, coalesced group store ----
#pragma unroll
        for (int mt = 0; mt < 3; mt++)
#pragma unroll
            for (int nt = 0; nt < 2; nt++) {
                int col = h * 16 + nt * 8 + 2 * t;
                int r0 = mt * 16 + g;
                *(__half2*)(Os + r0 * 136 + col) =
                    __floats2half2_rn(o[mt][nt][0] * inv[mt][0],
                                      o[mt][nt][1] * inv[mt][0]);
                *(__half2*)(Os + (r0 + 8) * 136 + col) =
                    __floats2half2_rn(o[mt][nt][2] * inv[mt][1],
                                      o[mt][nt][3] * inv[mt][1]);
            }
        NBAR(barid);

#pragma unroll
        for (int it = 0; it < 3; it++) {
            int idx = gtid + it * 256;
            int row = idx >> 4, c = idx & 15;
            *(uint4*)(g_o + (size_t)(bs + (long)row * stride) * 384
                      + axis * 128 + c * 8) = *(const uint4*)(Os + row * 136 + c * 8);
        }
    }
#undef BASE_OF
#undef STAGE_A
}

// ---------------------------------------------------------------------------
// fused tail: outproj(+bias3+res(g_xe)) -> LN1 -> mlp1(relu) -> mlp2(+res)
// -> LN2 -> transposed fp32 store. Intermediates never touch DRAM.
// ---------------------------------------------------------------------------
#define FUSE_SMEM 100864

struct FP {
    const float *bo0, *bo1, *bo2, *b1, *b2, *lng, *lnb;
    float* out;
};

__global__ __launch_bounds__(256, 2) void fuse_kernel(FP p)
{
    extern __shared__ __align__(16) char smc[];
    unsigned sR = (unsigned)__cvta_generic_to_shared(smc);
    unsigned sX = sR + 68096;
    float* Ct = (float*)smc;

    int tid = threadIdx.x, w = tid >> 5, lane = tid & 31;
    int mw = w & 3, nw = w >> 2;
    int g = lane >> 2, t = lane & 3;
    long m0 = (long)blockIdx.x * 128;

    int rowA  = mw * 32 + (lane & 15);
    int rowB0 = nw * 64 + ((lane & 16) >> 1) + (lane & 7);
    unsigned hiA = (unsigned)((lane >> 4) << 4);
    unsigned hiB = (unsigned)(((lane >> 3) & 1) << 4);
    unsigned xA = (unsigned)((rowA & 7) << 4);
    unsigned xB = (unsigned)((rowB0 & 7) << 4);

    // ================= P1: outproj, A=g_o (lda 384), B=wout_cat, K=384 ======
    float acc[2][8][4];
#pragma unroll
    for (int mt = 0; mt < 2; mt++)
#pragma unroll
        for (int nt = 0; nt < 8; nt++)
#pragma unroll
            for (int i = 0; i < 4; i++) acc[mt][nt][i] = 0.f;
    {
        unsigned sA = sR, sB = sR + 32768;
        const __half* Ap = g_o;
        const __half* Bp = g_wh + 147456;

#define STAGE1(c, buf) do {                                                   \
        int k0_ = (c) * 64;                                                   \
        _Pragma("unroll")                                                     \
        for (int i_ = 0; i_ < 4; i_++) {                                      \
            int idx_ = tid + 256 * i_;                                        \
            int row_ = idx_ >> 3, seg_ = idx_ & 7;                            \
            unsigned dcol_ = (unsigned)((seg_ * 16) ^ ((row_ & 7) << 4));     \
            cpa16_s(sA + (buf) * 16384 + row_ * 128 + dcol_,                  \
                    Ap + (m0 + row_) * 384 + k0_ + seg_ * 8);                 \
            cpa16_s(sB + (buf) * 16384 + row_ * 128 + dcol_,                  \
                    Bp + (size_t)row_ * 384 + k0_ + seg_ * 8);                \
        }                                                                     \
    } while (0)

        STAGE1(0, 0); CP_COMMIT();
        for (int c = 0; c < 6; c++) {
            if (c + 1 < 6) { STAGE1(c + 1, (c + 1) & 1); CP_COMMIT(); CP_WAIT1(); }
            else           { CP_WAIT0(); }
            __syncthreads();
            unsigned baseA = sA + (c & 1) * 16384;
            unsigned baseB = sB + (c & 1) * 16384;
#pragma unroll
            for (int kt = 0; kt < 4; kt++) {
                unsigned a[2][4];
#pragma unroll
                for (int mt = 0; mt < 2; mt++)
                    LDSM4(a[mt], baseA + (rowA + mt * 16) * 128
                                 + (((unsigned)(kt * 32) + hiA) ^ xA));
#pragma unroll
                for (int np = 0; np < 4; np++) {
                    unsigned b[4];
                    LDSM4(b, baseB + (rowB0 + np * 16) * 128
                             + (((unsigned)(kt * 32) + hiB) ^ xB));
                    MMA16(acc[0][2 * np],     a[0], b[0], b[1]);
                    MMA16(acc[1][2 * np],     a[1], b[0], b[1]);
                    MMA16(acc[0][2 * np + 1], a[0], b[2], b[3]);
                    MMA16(acc[1][2 * np + 1], a[1], b[2], b[3]);
                }
            }
            __syncthreads();
        }
#undef STAGE1
    }

    // epilogue P1: Ct = acc + (bo0+bo1+bo2) + g_xe residual
#pragma unroll
    for (int mt = 0; mt < 2; mt++)
#pragma unroll
        for (int nt = 0; nt < 8; nt++) {
            int rl = mw * 32 + mt * 16 + g;
            int cc = nw * 64 + nt * 8 + 2 * t;
            size_t tok = m0 + rl;
            float b0 = p.bo0[cc] + p.bo1[cc] + p.bo2[cc];
            float b1v = p.bo0[cc + 1] + p.bo1[cc + 1] + p.bo2[cc + 1];
            Ct[rl * 133 + cc]     = acc[mt][nt][0] + b0 + __half2float(g_xe[tok * 128 + cc]);
            Ct[rl * 133 + cc + 1] = acc[mt][nt][1] + b1v + __half2float(g_xe[tok * 128 + cc + 1]);
            Ct[(rl + 8) * 133 + cc]     = acc[mt][nt][2] + b0 + __half2float(g_xe[(tok + 8) * 128 + cc]);
            Ct[(rl + 8) * 133 + cc + 1] = acc[mt][nt][3] + b1v + __half2float(g_xe[(tok + 8) * 128 + cc + 1]);
        }
    __syncthreads();

    // LN1 -> xln (fp16 swizzled tile, row stride 256B)
    for (int r = w; r < 128; r += 8) {
        float v[4], s = 0.f, s2 = 0.f;
#pragma unroll
        for (int k = 0; k < 4; k++) {
            v[k] = Ct[r * 133 + lane + 32 * k];
            s += v[k]; s2 += v[k] * v[k];
        }
        for (int off = 16; off; off >>= 1) {
            s  += __shfl_xor_sync(0xffffffffu, s,  off);
            s2 += __shfl_xor_sync(0xffffffffu, s2, off);
        }
        float m   = s * (1.f / 128.f);
        float var = s2 * (1.f / 128.f) - m * m;
        float rs  = rsqrtf(var + 1e-5f);
        unsigned rxor = (unsigned)((r & 7) << 4);
#pragma unroll
        for (int k = 0; k < 4; k++) {
            int cc = lane + 32 * k;
            float y = (v[k] - m) * rs * p.lng[cc] + p.lnb[cc];
            *(__half*)(smc + 68096 + r * 256 + ((unsigned)(2 * cc) ^ rxor)) =
                __float2half(y);
        }
    }
    __syncthreads();

    // ================= stage w1 -> R1[0,32K), w2 -> R1[32K,64K) =============
    {
        const __half* w1p = g_wh + 196608;
        const __half* w2p = g_wh + 212992;
#pragma unroll
        for (int i = 0; i < 8; i++) {
            int idx = tid + i * 256;
            int row = idx >> 4, seg = idx & 15;
            unsigned dcol = (unsigned)((seg * 16) ^ ((row & 7) << 4));
            cpa16_s(sR + row * 256 + dcol, w1p + row * 128 + seg * 8);
            cpa16_s(sR + 32768 + row * 256 + dcol, w2p + row * 128 + seg * 8);
        }
        CP_COMMIT(); CP_WAIT0();
        __syncthreads();
    }

    // ================= P2: h = relu(xln @ w1^T + b1), K=128 =================
    float acc2[2][8][4];
#pragma unroll
    for (int mt = 0; mt < 2; mt++)
#pragma unroll
        for (int nt = 0; nt < 8; nt++)
#pragma unroll
            for (int i = 0; i < 4; i++) acc2[mt][nt][i] = 0.f;

#pragma unroll
    for (int kt = 0; kt < 8; kt++) {
        unsigned a[2][4];
#pragma unroll
        for (int mt = 0; mt < 2; mt++)
            LDSM4(a[mt], sX + (rowA + mt * 16) * 256
                         + (((unsigned)(kt * 32) + hiA) ^ xA));
#pragma unroll
        for (int np = 0; np < 4; np++) {
            unsigned b[4];
            LDSM4(b, sR + (rowB0 + np * 16) * 256
                     + (((unsigned)(kt * 32) + hiB) ^ xB));
            MMA16(acc2[0][2 * np],     a[0], b[0], b[1]);
            MMA16(acc2[1][2 * np],     a[1], b[0], b[1]);
            MMA16(acc2[0][2 * np + 1], a[0], b[2], b[3]);
            MMA16(acc2[1][2 * np + 1], a[1], b[2], b[3]);
        }
    }
    __syncthreads();

    // h tile (fp16 swizzled, row 256B) at R1[0,32K)
#pragma unroll
    for (int mt = 0; mt < 2; mt++)
#pragma unroll
        for (int nt = 0; nt < 8; nt++) {
            int rl = mw * 32 + mt * 16 + g;
            int cc = nw * 64 + nt * 8 + 2 * t;
            float b0 = p.b1[cc], b1v = p.b1[cc + 1];
            unsigned c2 = (unsigned)(2 * cc);
            *(__half2*)(smc + rl * 256 + (c2 ^ (unsigned)((rl & 7) << 4))) =
                __floats2half2_rn(fmaxf(acc2[mt][nt][0] + b0, 0.f),
                                  fmaxf(acc2[mt][nt][1] + b1v, 0.f));
            *(__half2*)(smc + (rl + 8) * 256 + (c2 ^ (unsigned)(((rl + 8) & 7) << 4))) =
                __floats2half2_rn(fmaxf(acc2[mt][nt][2] + b0, 0.f),
                                  fmaxf(acc2[mt][nt][3] + b1v, 0.f));
        }
    __syncthreads();

    // ================= P3: y = h @ w2^T + b2 + xln, K=128 ===================
    float acc3[2][8][4];
#pragma unroll
    for (int mt = 0; mt < 2; mt++)
#pragma unroll
        for (int nt = 0; nt < 8; nt++)
#pragma unroll
            for (int i = 0; i < 4; i++) acc3[mt][nt][i] = 0.f;

#pragma unroll
    for (int kt = 0; kt < 8; kt++) {
        unsigned a[2][4];
#pragma unroll
        for (int mt = 0; mt < 2; mt++)
            LDSM4(a[mt], sR + (rowA + mt * 16) * 256
                         + (((unsigned)(kt * 32) + hiA) ^ xA));
#pragma unroll
        for (int np = 0; np < 4; np++) {
            unsigned b[4];
            LDSM4(b, sR + 32768 + (rowB0 + np * 16) * 256
                     + (((unsigned)(kt * 32) + hiB) ^ xB));
            MMA16(acc3[0][2 * np],     a[0], b[0], b[1]);
            MMA16(acc3[1][2 * np],     a[1], b[0], b[1]);
            MMA16(acc3[0][2 * np + 1], a[0], b[2], b[3]);
            MMA16(acc3[1][2 * np + 1], a[1], b[2], b[3]);
        }
    }
    __syncthreads();

    // epilogue P3: Ct = acc3 + b2 + xln residual
#pragma unroll
    for (int mt = 0; mt < 2; mt++)
#pragma unroll
        for (int nt = 0; nt < 8; nt++) {
            int rl = mw * 32 + mt * 16 + g;
            int cc = nw * 64 + nt * 8 + 2 * t;
            float b0 = p.b2[cc], b1v = p.b2[cc + 1];
            unsigned c2 = (unsigned)(2 * cc);
            __half2 r0 = *(const __half2*)(smc + 68096 + rl * 256
                                           + (c2 ^ (unsigned)((rl & 7) << 4)));
            __half2 r1 = *(const __half2*)(smc + 68096 + (rl + 8) * 256
                                           + (c2 ^ (unsigned)(((rl + 8) & 7) << 4)));
            float2 f0 = __half22float2(r0);
            float2 f1 = __half22float2(r1);
            Ct[rl * 133 + cc]           = acc3[mt][nt][0] + b0 + f0.x;
            Ct[rl * 133 + cc + 1]       = acc3[mt][nt][1] + b1v + f0.y;
            Ct[(rl + 8) * 133 + cc]     = acc3[mt][nt][2] + b0 + f1.x;
            Ct[(rl + 8) * 133 + cc + 1] = acc3[mt][nt][3] + b1v + f1.y;
        }
    __syncthreads();

    // LN2 (in place in Ct)
    for (int r = w; r < 128; r += 8) {
        float v[4], s = 0.f, s2 = 0.f;
#pragma unroll
        for (int k = 0; k < 4; k++) {
            v[k] = Ct[r * 133 + lane + 32 * k];
            s += v[k]; s2 += v[k] * v[k];
        }
        for (int off = 16; off; off >>= 1) {
            s  += __shfl_xor_sync(0xffffffffu, s,  off);
            s2 += __shfl_xor_sync(0xffffffffu, s2, off);
        }
        float m   = s * (1.f / 128.f);
        float var = s2 * (1.f / 128.f) - m * m;
        float rs  = rsqrtf(var + 1e-5f);
#pragma unroll
        for (int k = 0; k < 4; k++) {
            int cc = lane + 32 * k;
            Ct[r * 133 + cc] = (v[k] - m) * rs * p.lng[cc] + p.lnb[cc];
        }
    }
    __syncthreads();

    // transposed fp32 store to (B,C,X,Y,Z)
    int  bi  = (int)(m0 / SS);
    long sp0 = m0 % SS;
    float* outp = p.out + (size_t)bi * 128 * SS + sp0;
    for (int e = tid; e < 128 * 128; e += 256) {
        int cc = e >> 7, ss = e & 127;
        outp[(size_t)cc * SS + ss] = Ct[ss * 133 + cc];
    }
}

// ---------------------------------------------------------------------------
// launch
// ---------------------------------------------------------------------------
extern "C" void kernel_launch(void* const* d_in, const int* in_sizes, int n_in,
                              void* d_out, int out_size)
{
    (void)in_sizes; (void)n_in; (void)out_size;
    const float* x    = (const float*)d_in[0];
    const float* px   = (const float*)d_in[1];
    const float* py   = (const float*)d_in[2];
    const float* pz   = (const float*)d_in[3];

    cudaFuncSetAttribute((const void*)attn3_kernel,
                         cudaFuncAttributeMaxDynamicSharedMemorySize, ATTN3_SMEM);
    cudaFuncSetAttribute((const void*)fuse_kernel,
                         cudaFuncAttributeMaxDynamicSharedMemorySize, FUSE_SMEM);

    WP wp;
    for (int a = 0; a < 3; a++) {
        wp.wq[a]   = (const float*)d_in[4 + 4 * a];
        wp.wkv[a]  = (const float*)d_in[5 + 4 * a];
        wp.wout[a] = (const float*)d_in[6 + 4 * a];
    }
    wp.w1 = (const float*)d_in[18];
    wp.w2 = (const float*)d_in[20];
    wconv_kernel<<<896, 256>>>(wp);

    prep_kernel<<<NT / 64, 256>>>(x, px, py, pz);

    attn3_kernel<<<dim3(288, 3), 512, ATTN3_SMEM>>>();

    FP fp;
    fp.bo0 = (const float*)d_in[7];
    fp.bo1 = (const float*)d_in[11];
    fp.bo2 = (const float*)d_in[15];
    fp.b1  = (const float*)d_in[19];
    fp.b2  = (const float*)d_in[21];
    fp.lng = (const float*)d_in[16];
    fp.lnb = (const float*)d_in[17];
    fp.out = (float*)d_out;
    fuse_kernel<<<NT / 128, 256, FUSE_SMEM>>>(fp);
}

// round 12
// speedup vs baseline: 1.0258x; 1.0248x over previous
#include <cuda_runtime.h>
#include <cuda_fp16.h>

// Problem constants
#define SS   110592          // 48^3
#define NT   221184          // NB*SS tokens

// Scratch (device globals; no allocation allowed) — all intermediates fp16
__device__ __half g_xe [NT * 128];            // pos-embedded input (residual 1)
__device__ __half g_o  [(size_t)NT * 384];    // attention outputs, 3 axes
// fp16 weights: [0,147456) qkv blocks (3 axes x [384][128]), [147456,196608)
// wout_cat (128 rows x 384), [196608,212992) w1, [212992,229376) w2
__device__ __half g_wh [229376];

// ---------------------------------------------------------------------------
// helpers
// ---------------------------------------------------------------------------
__device__ __forceinline__ void cpa16_s(unsigned d, const void* s) {
    asm volatile("cp.async.cg.shared.global [%0], [%1], 16;" :: "r"(d), "l"(s));
}
#define CP_COMMIT() asm volatile("cp.async.commit_group;")
#define CP_WAIT1()  asm volatile("cp.async.wait_group 1;")
#define CP_WAIT0()  asm volatile("cp.async.wait_group 0;")

#define LDSM4(r, addr) \
    asm volatile("ldmatrix.sync.aligned.m8n8.x4.shared.b16 {%0,%1,%2,%3}, [%4];" \
        : "=r"((r)[0]), "=r"((r)[1]), "=r"((r)[2]), "=r"((r)[3]) : "r"(addr))

#define LDSM4T(r, addr) \
    asm volatile("ldmatrix.sync.aligned.m8n8.x4.trans.shared.b16 {%0,%1,%2,%3}, [%4];" \
        : "=r"((r)[0]), "=r"((r)[1]), "=r"((r)[2]), "=r"((r)[3]) : "r"(addr))

#define MMA16(d, a, b0, b1) \
    asm volatile("mma.sync.aligned.m16n8k16.row.col.f32.f16.f16.f32 " \
        "{%0,%1,%2,%3}, {%4,%5,%6,%7}, {%8,%9}, {%0,%1,%2,%3};" \
        : "+f"((d)[0]), "+f"((d)[1]), "+f"((d)[2]), "+f"((d)[3]) \
        : "r"((a)[0]), "r"((a)[1]), "r"((a)[2]), "r"((a)[3]), \
          "r"(b0), "r"(b1))

#define NBAR(id) asm volatile("bar.sync %0, 256;" :: "r"(id) : "memory")

__device__ __forceinline__ unsigned h2u(float x, float y) {
    __half2 h = __floats2half2_rn(x, y);
    return *(unsigned*)&h;
}

// ---------------------------------------------------------------------------
// weight convert: fp32 -> fp16 buffer, one-time layout
// ---------------------------------------------------------------------------
struct WP {
    const float* wq[3]; const float* wkv[3]; const float* wout[3];
    const float* w1; const float* w2;
};
__global__ __launch_bounds__(256) void wconv_kernel(WP p)
{
    int idx = blockIdx.x * 256 + threadIdx.x;
    if (idx >= 229376) return;
    float v;
    if (idx < 147456) {
        int strip = idx >> 14, rem = idx & 16383;
        int a = strip / 3, r = strip - a * 3;
        v = (r == 0) ? p.wq[a][rem] : p.wkv[a][(r - 1) * 16384 + rem];
    } else if (idx < 196608) {
        int rem = idx - 147456;
        int n = rem / 384, k = rem - n * 384;
        v = p.wout[k >> 7][n * 128 + (k & 127)];
    } else if (idx < 212992) v = p.w1[idx - 196608];
    else                     v = p.w2[idx - 212992];
    g_wh[idx] = __float2half(v);
}

// ---------------------------------------------------------------------------
// prep: xe = 2*x + px + py + pz, transpose (B,C,S) -> (token, C), fp16
// vectorized: float2 global reads, half2 writes, fully unrolled
// ---------------------------------------------------------------------------
__global__ __launch_bounds__(256) void prep_kernel(
    const float* __restrict__ x,  const float* __restrict__ px,
    const float* __restrict__ py, const float* __restrict__ pz)
{
    __shared__ float tile[64][130];
    int base = blockIdx.x * 64;
    int b    = base / SS;
    int sp0  = base % SS;

#pragma unroll
    for (int k = 0; k < 16; k++) {           // 4096 float2 chunks
        int e  = threadIdx.x + k * 256;
        int c  = e >> 5;                     // 0..127
        int s2 = (e & 31) * 2;               // 0..62 (even)
        int spatial = sp0 + s2;
        float2 xv = *(const float2*)(x + (size_t)b * 128 * SS
                                       + (size_t)c * SS + spatial);
        int zi0 = spatial % 48, r0 = spatial / 48;
        int yi0 = r0 % 48,      xi0 = r0 / 48;
        int sp1 = spatial + 1;
        int zi1 = sp1 % 48,     r1 = sp1 / 48;
        int yi1 = r1 % 48,      xi1 = r1 / 48;
        tile[s2][c]     = 2.0f * xv.x + px[c * 48 + xi0] + py[c * 48 + yi0]
                        + pz[c * 48 + zi0];
        tile[s2 + 1][c] = 2.0f * xv.y + px[c * 48 + xi1] + py[c * 48 + yi1]
                        + pz[c * 48 + zi1];
    }
    __syncthreads();
#pragma unroll
    for (int k = 0; k < 16; k++) {           // 4096 half2 outputs
        int e  = threadIdx.x + k * 256;
        int s  = e >> 6;
        int c2 = (e & 63) * 2;
        *(__half2*)(g_xe + (size_t)(base + s) * 128 + c2) =
            __floats2half2_rn(tile[s][c2], tile[s][c2 + 1]);
    }
}

// ---------------------------------------------------------------------------
// fused QKV + attention v3: grid (288, 3 axes); 512 threads = 2 warp-groups.
// Each group processes 8 interleaved sequences with private A (2x12KB) and
// KV (36KB) buffers; both share the axis weight tile W (96KB). Warp = head:
// warp h computes its head's q/k/v columns; Q stays in registers (C-frag ->
// A-frag repack, softmax scale folded into the pack), K/V go to warp-private
// smem. Group sync via named barriers.
// ---------------------------------------------------------------------------
#define ATTN3_SMEM 221184
#define EXP2_SCALE 0.36067376022224085f   // 0.25 * log2(e)

__global__ __launch_bounds__(512, 1) void attn3_kernel()
{
    extern __shared__ __align__(16) char smc[];
    unsigned sbase = (unsigned)__cvta_generic_to_shared(smc);
    const unsigned sW = sbase;

    int tid  = threadIdx.x;
    int gid  = tid >> 8;           // warp-group 0/1
    int gtid = tid & 255;
    int lane = tid & 31;
    int h    = (gtid >> 5);        // warp in group = head
    int g    = lane >> 2, t = lane & 3;

    unsigned gA  = sbase + 98304 + (unsigned)gid * 61440;  // 2 x 12288
    unsigned gKV = gA + 24576;                             // 36864 (K,V)
    char*   KVc  = smc + 98304 + gid * 61440 + 24576;
    __half* Os   = (__half*)KVc;                           // aliases KV

    int axis = blockIdx.y;
    int stride = (axis == 0) ? 2304 : (axis == 1 ? 48 : 1);

    // ---- stage W (384 rows x 256B swizzled), all 512 threads ----
    const __half* Wsrc = g_wh + (size_t)axis * 49152;
#pragma unroll
    for (int i = 0; i < 12; i++) {
        int idx = tid + i * 512;
        int row = idx >> 4, seg = idx & 15;
        cpa16_s(sW + row * 256 + (unsigned)((seg * 16) ^ ((row & 7) << 4)),
                Wsrc + (size_t)row * 128 + seg * 8);
    }
    CP_COMMIT();

#define BASE_OF(sq, bs) do {                                                  \
        int b_ = (sq) / 2304, rr_ = (sq) % 2304;                              \
        int o1_ = rr_ / 48, o2_ = rr_ % 48;                                   \
        if (axis == 0)      bs = (long)b_ * SS + o1_ * 48 + o2_;              \
        else if (axis == 1) bs = (long)b_ * SS + o1_ * 2304 + o2_;            \
        else                bs = (long)b_ * SS + o1_ * 2304 + (long)o2_ * 48; \
    } while (0)

#define STAGE_A(bs, buf) do {                                                 \
        _Pragma("unroll")                                                     \
        for (int it_ = 0; it_ < 3; it_++) {                                   \
            int idx_ = gtid + it_ * 256;                                      \
            int row_ = idx_ >> 4, seg_ = idx_ & 15;                           \
            cpa16_s(gA + (buf) * 12288 + row_ * 256                           \
                    + (unsigned)((seg_ * 16) ^ ((row_ & 7) << 4)),            \
                    g_xe + (size_t)((bs) + (long)row_ * stride) * 128         \
                    + seg_ * 8);                                              \
        }                                                                     \
    } while (0)

    int seqbase = blockIdx.x * 16 + gid;     // group's seqs: +2 per step
    { long bs0; BASE_OF(seqbase, bs0); STAGE_A(bs0, 0); }
    CP_COMMIT();
    CP_WAIT1();          // W complete (A0 still in flight)
    __syncthreads();     // W visible CTA-wide

    // fragment addressing constants
    unsigned hiA = (unsigned)((lane >> 4) << 4);
    unsigned xA  = (unsigned)((lane & 7) << 4);
    int raL  = lane & 15;
    int rbL  = ((lane & 16) >> 1) + (lane & 7);
    unsigned hiB = (unsigned)(((lane >> 3) & 1) << 4);
    unsigned xB  = (unsigned)((lane & 7) << 4);
    int barid = gid + 1;

    for (int i = 0; i < 8; i++) {
        long bs; BASE_OF(seqbase + 2 * i, bs);
        if (i + 1 < 8) {
            long bn; BASE_OF(seqbase + 2 * (i + 1), bn);
            STAGE_A(bn, (i + 1) & 1);
            CP_COMMIT(); CP_WAIT1();
        } else {
            CP_WAIT0();
        }
        NBAR(barid);     // A(i) visible group-wide; prior seq fully done

        // ---- GEMM: warp computes its head's q|k|v (48 cols), M=48, K=128 --
        unsigned sAc = gA + (unsigned)((i & 1) * 12288);
        float acc[3][6][4];
#pragma unroll
        for (int mt = 0; mt < 3; mt++)
#pragma unroll
            for (int nt = 0; nt < 6; nt++)
#pragma unroll
                for (int q = 0; q < 4; q++) acc[mt][nt][q] = 0.f;

#pragma unroll
        for (int kt = 0; kt < 8; kt++) {
            unsigned a[3][4];
#pragma unroll
            for (int mt = 0; mt < 3; mt++)
                LDSM4(a[mt], sAc + (unsigned)((mt * 16 + raL) * 256)
                             + (((unsigned)(kt * 32) + hiA) ^ xA));
#pragma unroll
            for (int np = 0; np < 3; np++) {
                int rowb = np * 128 + h * 16 + rbL;
                unsigned b[4];
                LDSM4(b, sW + (unsigned)(rowb * 256)
                         + (((unsigned)(kt * 32) + hiB) ^ xB));
#pragma unroll
                for (int mt = 0; mt < 3; mt++) {
                    MMA16(acc[mt][2 * np],     a[mt], b[0], b[1]);
                    MMA16(acc[mt][2 * np + 1], a[mt], b[2], b[3]);
                }
            }
        }

        // ---- Q: C-frag -> A-frag repack with softmax scale folded in ----
        unsigned qf[3][4];
#pragma unroll
        for (int mt = 0; mt < 3; mt++) {
            qf[mt][0] = h2u(acc[mt][0][0] * EXP2_SCALE, acc[mt][0][1] * EXP2_SCALE);
            qf[mt][1] = h2u(acc[mt][0][2] * EXP2_SCALE, acc[mt][0][3] * EXP2_SCALE);
            qf[mt][2] = h2u(acc[mt][1][0] * EXP2_SCALE, acc[mt][1][1] * EXP2_SCALE);
            qf[mt][3] = h2u(acc[mt][1][2] * EXP2_SCALE, acc[mt][1][3] * EXP2_SCALE);
        }
        // ---- K,V -> warp-private smem (48B rows) ----
#pragma unroll
        for (int np = 1; np < 3; np++)
#pragma unroll
            for (int nts = 0; nts < 2; nts++) {
                int nt = np * 2 + nts;
                char* dst = KVc + (np - 1) * 18432 + h * 2304
                          + (nts * 8 + 2 * t) * 2;
#pragma unroll
                for (int mt = 0; mt < 3; mt++) {
                    int r0 = mt * 16 + g;
                    *(__half2*)(dst + r0 * 48) =
                        __floats2half2_rn(acc[mt][nt][0], acc[mt][nt][1]);
                    *(__half2*)(dst + (r0 + 8) * 48) =
                        __floats2half2_rn(acc[mt][nt][2], acc[mt][nt][3]);
                }
            }
        __syncwarp();

        // ---- scores S = Qs @ K^T (Q pre-scaled) ----
        unsigned Kb = gKV + (unsigned)(h * 2304);
        unsigned Vb = Kb + 18432u;
        float s[3][6][4];
#pragma unroll
        for (int mt = 0; mt < 3; mt++)
#pragma unroll
            for (int nt = 0; nt < 6; nt++)
#pragma unroll
                for (int q = 0; q < 4; q++) s[mt][nt][q] = 0.f;
#pragma unroll
        for (int nt2 = 0; nt2 < 3; nt2++) {
            unsigned bb[4];
            LDSM4(bb, Kb + (unsigned)((nt2 * 16 + rbL) * 48) + hiB);
#pragma unroll
            for (int mt = 0; mt < 3; mt++) {
                MMA16(s[mt][2 * nt2],     qf[mt], bb[0], bb[1]);
                MMA16(s[mt][2 * nt2 + 1], qf[mt], bb[2], bb[3]);
            }
        }

        // ---- max-free softmax (raw exp2), norm deferred to O ----
        float inv[3][2];
#pragma unroll
        for (int mt = 0; mt < 3; mt++)
#pragma unroll
            for (int hi = 0; hi < 2; hi++) {
                float sum = 0.f;
#pragma unroll
                for (int nt = 0; nt < 6; nt++)
#pragma unroll
                    for (int lo = 0; lo < 2; lo++) {
                        float e = exp2f(s[mt][nt][hi * 2 + lo]);
                        s[mt][nt][hi * 2 + lo] = e;
                        sum += e;
                    }
                sum += __shfl_xor_sync(0xffffffffu, sum, 1);
                sum += __shfl_xor_sync(0xffffffffu, sum, 2);
                inv[mt][hi] = 1.f / sum;
            }

        // ---- O = P_unnorm @ V ----
        float o[3][2][4];
#pragma unroll
        for (int mt = 0; mt < 3; mt++)
#pragma unroll
            for (int nt = 0; nt < 2; nt++)
#pragma unroll
                for (int q = 0; q < 4; q++) o[mt][nt][q] = 0.f;
#pragma unroll
        for (int kt = 0; kt < 3; kt++) {
            unsigned vb[4];
            LDSM4T(vb, Vb + (unsigned)((kt * 16 + raL) * 48) + hiA);
            unsigned pa[3][4];
#pragma unroll
            for (int mt = 0; mt < 3; mt++) {
                pa[mt][0] = h2u(s[mt][2 * kt][0],     s[mt][2 * kt][1]);
                pa[mt][1] = h2u(s[mt][2 * kt][2],     s[mt][2 * kt][3]);
                pa[mt][2] = h2u(s[mt][2 * kt + 1][0], s[mt][2 * kt + 1][1]);
                pa[mt][3] = h2u(s[mt][2 * kt + 1][2], s[mt][2 * kt + 1][3]);
            }
#pragma unroll
            for (int mt = 0; mt < 3; mt++) {
                MMA16(o[mt][0], pa[mt], vb[0], vb[1]);
                MMA16(o[mt][1], pa[mt], vb[2], vb[3]);
            }
        }

        NBAR(barid);   // all group warps done reading K/V (Os aliases KV)

        // ---- normalize O, stage, coalesced group store ----
#pragma unroll
        for (int mt = 0; mt < 3; mt++)
#pragma unroll
            for (int nt = 0; nt < 2; nt++) {
                int col = h * 16 + nt * 8 + 2 * t;
                int r0 = mt * 16 + g;
                *(__half2*)(Os + r0 * 136 + col) =
                    __floats2half2_rn(o[mt][nt][0] * inv[mt][0],
                                      o[mt][nt][1] * inv[mt][0]);
                *(__half2*)(Os + (r0 + 8) * 136 + col) =
                    __floats2half2_rn(o[mt][nt][2] * inv[mt][1],
                                      o[mt][nt][3] * inv[mt][1]);
            }
        NBAR(barid);

#pragma unroll
        for (int it = 0; it < 3; it++) {
            int idx = gtid + it * 256;
            int row = idx >> 4, c = idx & 15;
            *(uint4*)(g_o + (size_t)(bs + (long)row * stride) * 384
                      + axis * 128 + c * 8) = *(const uint4*)(Os + row * 136 + c * 8);
        }
    }
#undef BASE_OF
#undef STAGE_A
}

// ---------------------------------------------------------------------------
// fused tail: outproj(+bias3+res(g_xe)) -> LN1 -> mlp1(relu) -> mlp2(+res)
// -> LN2 -> transposed fp32 store. Intermediates never touch DRAM.
// ---------------------------------------------------------------------------
#define FUSE_SMEM 100864

struct FP {
    const float *bo0, *bo1, *bo2, *b1, *b2, *lng, *lnb;
    float* out;
};

__global__ __launch_bounds__(256, 2) void fuse_kernel(FP p)
{
    extern __shared__ __align__(16) char smc[];
    unsigned sR = (unsigned)__cvta_generic_to_shared(smc);
    unsigned sX = sR + 68096;
    float* Ct = (float*)smc;

    int tid = threadIdx.x, w = tid >> 5, lane = tid & 31;
    int mw = w & 3, nw = w >> 2;
    int g = lane >> 2, t = lane & 3;
    long m0 = (long)blockIdx.x * 128;

    int rowA  = mw * 32 + (lane & 15);
    int rowB0 = nw * 64 + ((lane & 16) >> 1) + (lane & 7);
    unsigned hiA = (unsigned)((lane >> 4) << 4);
    unsigned hiB = (unsigned)(((lane >> 3) & 1) << 4);
    unsigned xA = (unsigned)((rowA & 7) << 4);
    unsigned xB = (unsigned)((rowB0 & 7) << 4);

    // ================= P1: outproj, A=g_o (lda 384), B=wout_cat, K=384 ======
    float acc[2][8][4];
#pragma unroll
    for (int mt = 0; mt < 2; mt++)
#pragma unroll
        for (int nt = 0; nt < 8; nt++)
#pragma unroll
            for (int i = 0; i < 4; i++) acc[mt][nt][i] = 0.f;
    {
        unsigned sA = sR, sB = sR + 32768;
        const __half* Ap = g_o;
        const __half* Bp = g_wh + 147456;

#define STAGE1(c, buf) do {                                                   \
        int k0_ = (c) * 64;                                                   \
        _Pragma("unroll")                                                     \
        for (int i_ = 0; i_ < 4; i_++) {                                      \
            int idx_ = tid + 256 * i_;                                        \
            int row_ = idx_ >> 3, seg_ = idx_ & 7;                            \
            unsigned dcol_ = (unsigned)((seg_ * 16) ^ ((row_ & 7) << 4));     \
            cpa16_s(sA + (buf) * 16384 + row_ * 128 + dcol_,                  \
                    Ap + (m0 + row_) * 384 + k0_ + seg_ * 8);                 \
            cpa16_s(sB + (buf) * 16384 + row_ * 128 + dcol_,                  \
                    Bp + (size_t)row_ * 384 + k0_ + seg_ * 8);                \
        }                                                                     \
    } while (0)

        STAGE1(0, 0); CP_COMMIT();
        for (int c = 0; c < 6; c++) {
            if (c + 1 < 6) { STAGE1(c + 1, (c + 1) & 1); CP_COMMIT(); CP_WAIT1(); }
            else           { CP_WAIT0(); }
            __syncthreads();
            unsigned baseA = sA + (c & 1) * 16384;
            unsigned baseB = sB + (c & 1) * 16384;
#pragma unroll
            for (int kt = 0; kt < 4; kt++) {
                unsigned a[2][4];
#pragma unroll
                for (int mt = 0; mt < 2; mt++)
                    LDSM4(a[mt], baseA + (rowA + mt * 16) * 128
                                 + (((unsigned)(kt * 32) + hiA) ^ xA));
#pragma unroll
                for (int np = 0; np < 4; np++) {
                    unsigned b[4];
                    LDSM4(b, baseB + (rowB0 + np * 16) * 128
                             + (((unsigned)(kt * 32) + hiB) ^ xB));
                    MMA16(acc[0][2 * np],     a[0], b[0], b[1]);
                    MMA16(acc[1][2 * np],     a[1], b[0], b[1]);
                    MMA16(acc[0][2 * np + 1], a[0], b[2], b[3]);
                    MMA16(acc[1][2 * np + 1], a[1], b[2], b[3]);
                }
            }
            __syncthreads();
        }
#undef STAGE1
    }

    // epilogue P1: Ct = acc + (bo0+bo1+bo2) + g_xe residual (half2 loads)
#pragma unroll
    for (int mt = 0; mt < 2; mt++)
#pragma unroll
        for (int nt = 0; nt < 8; nt++) {
            int rl = mw * 32 + mt * 16 + g;
            int cc = nw * 64 + nt * 8 + 2 * t;
            size_t tok = m0 + rl;
            float b0 = p.bo0[cc] + p.bo1[cc] + p.bo2[cc];
            float b1v = p.bo0[cc + 1] + p.bo1[cc + 1] + p.bo2[cc + 1];
            float2 r0 = __half22float2(*(const __half2*)(g_xe + tok * 128 + cc));
            float2 r1 = __half22float2(*(const __half2*)(g_xe + (tok + 8) * 128 + cc));
            Ct[rl * 133 + cc]           = acc[mt][nt][0] + b0 + r0.x;
            Ct[rl * 133 + cc + 1]       = acc[mt][nt][1] + b1v + r0.y;
            Ct[(rl + 8) * 133 + cc]     = acc[mt][nt][2] + b0 + r1.x;
            Ct[(rl + 8) * 133 + cc + 1] = acc[mt][nt][3] + b1v + r1.y;
        }
    __syncthreads();

    // LN1 -> xln (fp16 swizzled tile, row stride 256B)
    for (int r = w; r < 128; r += 8) {
        float v[4], s = 0.f, s2 = 0.f;
#pragma unroll
        for (int k = 0; k < 4; k++) {
            v[k] = Ct[r * 133 + lane + 32 * k];
            s += v[k]; s2 += v[k] * v[k];
        }
        for (int off = 16; off; off >>= 1) {
            s  += __shfl_xor_sync(0xffffffffu, s,  off);
            s2 += __shfl_xor_sync(0xffffffffu, s2, off);
        }
        float m   = s * (1.f / 128.f);
        float var = s2 * (1.f / 128.f) - m * m;
        float rs  = rsqrtf(var + 1e-5f);
        unsigned rxor = (unsigned)((r & 7) << 4);
#pragma unroll
        for (int k = 0; k < 4; k++) {
            int cc = lane + 32 * k;
            float y = (v[k] - m) * rs * p.lng[cc] + p.lnb[cc];
            *(__half*)(smc + 68096 + r * 256 + ((unsigned)(2 * cc) ^ rxor)) =
                __float2half(y);
        }
    }
    __syncthreads();

    // ================= stage w1 -> R1[0,32K), w2 -> R1[32K,64K) =============
    {
        const __half* w1p = g_wh + 196608;
        const __half* w2p = g_wh + 212992;
#pragma unroll
        for (int i = 0; i < 8; i++) {
            int idx = tid + i * 256;
            int row = idx >> 4, seg = idx & 15;
            unsigned dcol = (unsigned)((seg * 16) ^ ((row & 7) << 4));
            cpa16_s(sR + row * 256 + dcol, w1p + row * 128 + seg * 8);
            cpa16_s(sR + 32768 + row * 256 + dcol, w2p + row * 128 + seg * 8);
        }
        CP_COMMIT(); CP_WAIT0();
        __syncthreads();
    }

    // ================= P2: h = relu(xln @ w1^T + b1), K=128 =================
    float acc2[2][8][4];
#pragma unroll
    for (int mt = 0; mt < 2; mt++)
#pragma unroll
        for (int nt = 0; nt < 8; nt++)
#pragma unroll
            for (int i = 0; i < 4; i++) acc2[mt][nt][i] = 0.f;

#pragma unroll
    for (int kt = 0; kt < 8; kt++) {
        unsigned a[2][4];
#pragma unroll
        for (int mt = 0; mt < 2; mt++)
            LDSM4(a[mt], sX + (rowA + mt * 16) * 256
                         + (((unsigned)(kt * 32) + hiA) ^ xA));
#pragma unroll
        for (int np = 0; np < 4; np++) {
            unsigned b[4];
            LDSM4(b, sR + (rowB0 + np * 16) * 256
                     + (((unsigned)(kt * 32) + hiB) ^ xB));
            MMA16(acc2[0][2 * np],     a[0], b[0], b[1]);
            MMA16(acc2[1][2 * np],     a[1], b[0], b[1]);
            MMA16(acc2[0][2 * np + 1], a[0], b[2], b[3]);
            MMA16(acc2[1][2 * np + 1], a[1], b[2], b[3]);
        }
    }
    __syncthreads();

    // h tile (fp16 swizzled, row 256B) at R1[0,32K)
#pragma unroll
    for (int mt = 0; mt < 2; mt++)
#pragma unroll
        for (int nt = 0; nt < 8; nt++) {
            int rl = mw * 32 + mt * 16 + g;
            int cc = nw * 64 + nt * 8 + 2 * t;
            float b0 = p.b1[cc], b1v = p.b1[cc + 1];
            unsigned c2 = (unsigned)(2 * cc);
            *(__half2*)(smc + rl * 256 + (c2 ^ (unsigned)((rl & 7) << 4))) =
                __floats2half2_rn(fmaxf(acc2[mt][nt][0] + b0, 0.f),
                                  fmaxf(acc2[mt][nt][1] + b1v, 0.f));
            *(__half2*)(smc + (rl + 8) * 256 + (c2 ^ (unsigned)(((rl + 8) & 7) << 4))) =
                __floats2half2_rn(fmaxf(acc2[mt][nt][2] + b0, 0.f),
                                  fmaxf(acc2[mt][nt][3] + b1v, 0.f));
        }
    __syncthreads();

    // ================= P3: y = h @ w2^T + b2 + xln, K=128 ===================
    float acc3[2][8][4];
#pragma unroll
    for (int mt = 0; mt < 2; mt++)
#pragma unroll
        for (int nt = 0; nt < 8; nt++)
#pragma unroll
            for (int i = 0; i < 4; i++) acc3[mt][nt][i] = 0.f;

#pragma unroll
    for (int kt = 0; kt < 8; kt++) {
        unsigned a[2][4];
#pragma unroll
        for (int mt = 0; mt < 2; mt++)
            LDSM4(a[mt], sR + (rowA + mt * 16) * 256
                         + (((unsigned)(kt * 32) + hiA) ^ xA));
#pragma unroll
        for (int np = 0; np < 4; np++) {
            unsigned b[4];
            LDSM4(b, sR + 32768 + (rowB0 + np * 16) * 256
                     + (((unsigned)(kt * 32) + hiB) ^ xB));
            MMA16(acc3[0][2 * np],     a[0], b[0], b[1]);
            MMA16(acc3[1][2 * np],     a[1], b[0], b[1]);
            MMA16(acc3[0][2 * np + 1], a[0], b[2], b[3]);
            MMA16(acc3[1][2 * np + 1], a[1], b[2], b[3]);
        }
    }
    __syncthreads();

    // epilogue P3: Ct = acc3 + b2 + xln residual
#pragma unroll
    for (int mt = 0; mt < 2; mt++)
#pragma unroll
        for (int nt = 0; nt < 8; nt++) {
            int rl = mw * 32 + mt * 16 + g;
            int cc = nw * 64 + nt * 8 + 2 * t;
            float b0 = p.b2[cc], b1v = p.b2[cc + 1];
            unsigned c2 = (unsigned)(2 * cc);
            __half2 r0 = *(const __half2*)(smc + 68096 + rl * 256
                                           + (c2 ^ (unsigned)((rl & 7) << 4)));
            __half2 r1 = *(const __half2*)(smc + 68096 + (rl + 8) * 256
                                           + (c2 ^ (unsigned)(((rl + 8) & 7) << 4)));
            float2 f0 = __half22float2(r0);
            float2 f1 = __half22float2(r1);
            Ct[rl * 133 + cc]           = acc3[mt][nt][0] + b0 + f0.x;
            Ct[rl * 133 + cc + 1]       = acc3[mt][nt][1] + b1v + f0.y;
            Ct[(rl + 8) * 133 + cc]     = acc3[mt][nt][2] + b0 + f1.x;
            Ct[(rl + 8) * 133 + cc + 1] = acc3[mt][nt][3] + b1v + f1.y;
        }
    __syncthreads();

    // LN2 (in place in Ct)
    for (int r = w; r < 128; r += 8) {
        float v[4], s = 0.f, s2 = 0.f;
#pragma unroll
        for (int k = 0; k < 4; k++) {
            v[k] = Ct[r * 133 + lane + 32 * k];
            s += v[k]; s2 += v[k] * v[k];
        }
        for (int off = 16; off; off >>= 1) {
            s  += __shfl_xor_sync(0xffffffffu, s,  off);
            s2 += __shfl_xor_sync(0xffffffffu, s2, off);
        }
        float m   = s * (1.f / 128.f);
        float var = s2 * (1.f / 128.f) - m * m;
        float rs  = rsqrtf(var + 1e-5f);
#pragma unroll
        for (int k = 0; k < 4; k++) {
            int cc = lane + 32 * k;
            Ct[r * 133 + cc] = (v[k] - m) * rs * p.lng[cc] + p.lnb[cc];
        }
    }
    __syncthreads();

    // transposed fp32 store to (B,C,X,Y,Z)
    int  bi  = (int)(m0 / SS);
    long sp0 = m0 % SS;
    float* outp = p.out + (size_t)bi * 128 * SS + sp0;
    for (int e = tid; e < 128 * 128; e += 256) {
        int cc = e >> 7, ss = e & 127;
        outp[(size_t)cc * SS + ss] = Ct[ss * 133 + cc];
    }
}

// ---------------------------------------------------------------------------
// launch
// ---------------------------------------------------------------------------
extern "C" void kernel_launch(void* const* d_in, const int* in_sizes, int n_in,
                              void* d_out, int out_size)
{
    (void)in_sizes; (void)n_in; (void)out_size;
    const float* x    = (const float*)d_in[0];
    const float* px   = (const float*)d_in[1];
    const float* py   = (const float*)d_in[2];
    const float* pz   = (const float*)d_in[3];

    cudaFuncSetAttribute((const void*)attn3_kernel,
                         cudaFuncAttributeMaxDynamicSharedMemorySize, ATTN3_SMEM);
    cudaFuncSetAttribute((const void*)fuse_kernel,
                         cudaFuncAttributeMaxDynamicSharedMemorySize, FUSE_SMEM);

    WP wp;
    for (int a = 0; a < 3; a++) {
        wp.wq[a]   = (const float*)d_in[4 + 4 * a];
        wp.wkv[a]  = (const float*)d_in[5 + 4 * a];
        wp.wout[a] = (const float*)d_in[6 + 4 * a];
    }
    wp.w1 = (const float*)d_in[18];
    wp.w2 = (const float*)d_in[20];
    wconv_kernel<<<896, 256>>>(wp);

    prep_kernel<<<NT / 64, 256>>>(x, px, py, pz);

    attn3_kernel<<<dim3(288, 3), 512, ATTN3_SMEM>>>();

    FP fp;
    fp.bo0 = (const float*)d_in[7];
    fp.bo1 = (const float*)d_in[11];
    fp.bo2 = (const float*)d_in[15];
    fp.b1  = (const float*)d_in[19];
    fp.b2  = (const float*)d_in[21];
    fp.lng = (const float*)d_in[16];
    fp.lnb = (const float*)d_in[17];
    fp.out = (float*)d_out;
    fuse_kernel<<<NT / 128, 256, FUSE_SMEM>>>(fp);
}

// round 13
// speedup vs baseline: 1.1868x; 1.1569x over previous
#include <cuda_runtime.h>
#include <cuda_fp16.h>

// Problem constants
#define SS   110592          // 48^3
#define NT   221184          // NB*SS tokens

// Scratch (device globals; no allocation allowed) — all intermediates fp16
__device__ __half g_xe [NT * 128];            // pos-embedded input (residual 1)
__device__ __half g_o  [(size_t)NT * 384];    // attention outputs, 3 axes
// fp16 weights: [0,147456) qkv blocks (3 axes x [384][128]), [147456,196608)
// wout_cat (128 rows x 384), [196608,212992) w1, [212992,229376) w2
__device__ __half g_wh [229376];

// ---------------------------------------------------------------------------
// helpers
// ---------------------------------------------------------------------------
__device__ __forceinline__ void cpa16_s(unsigned d, const void* s) {
    asm volatile("cp.async.cg.shared.global [%0], [%1], 16;" :: "r"(d), "l"(s));
}
#define CP_COMMIT() asm volatile("cp.async.commit_group;")
#define CP_WAIT1()  asm volatile("cp.async.wait_group 1;")
#define CP_WAIT0()  asm volatile("cp.async.wait_group 0;")

#define LDSM4(r, addr) \
    asm volatile("ldmatrix.sync.aligned.m8n8.x4.shared.b16 {%0,%1,%2,%3}, [%4];" \
        : "=r"((r)[0]), "=r"((r)[1]), "=r"((r)[2]), "=r"((r)[3]) : "r"(addr))

#define LDSM4T(r, addr) \
    asm volatile("ldmatrix.sync.aligned.m8n8.x4.trans.shared.b16 {%0,%1,%2,%3}, [%4];" \
        : "=r"((r)[0]), "=r"((r)[1]), "=r"((r)[2]), "=r"((r)[3]) : "r"(addr))

#define MMA16(d, a, b0, b1) \
    asm volatile("mma.sync.aligned.m16n8k16.row.col.f32.f16.f16.f32 " \
        "{%0,%1,%2,%3}, {%4,%5,%6,%7}, {%8,%9}, {%0,%1,%2,%3};" \
        : "+f"((d)[0]), "+f"((d)[1]), "+f"((d)[2]), "+f"((d)[3]) \
        : "r"((a)[0]), "r"((a)[1]), "r"((a)[2]), "r"((a)[3]), \
          "r"(b0), "r"(b1))

#define NBAR(id) asm volatile("bar.sync %0, 256;" :: "r"(id) : "memory")

#define EX2H2(r) asm("ex2.approx.f16x2 %0, %0;" : "+r"(r))

__device__ __forceinline__ unsigned h2u(float x, float y) {
    __half2 h = __floats2half2_rn(x, y);
    return *(unsigned*)&h;
}
__device__ __forceinline__ __half2 u2h(unsigned u) {
    __half2 h; *(unsigned*)&h = u; return h;
}

// ---------------------------------------------------------------------------
// weight convert: fp32 -> fp16 buffer, one-time layout
// ---------------------------------------------------------------------------
struct WP {
    const float* wq[3]; const float* wkv[3]; const float* wout[3];
    const float* w1; const float* w2;
};
__global__ __launch_bounds__(256) void wconv_kernel(WP p)
{
    int idx = blockIdx.x * 256 + threadIdx.x;
    if (idx >= 229376) return;
    float v;
    if (idx < 147456) {
        int strip = idx >> 14, rem = idx & 16383;
        int a = strip / 3, r = strip - a * 3;
        v = (r == 0) ? p.wq[a][rem] : p.wkv[a][(r - 1) * 16384 + rem];
    } else if (idx < 196608) {
        int rem = idx - 147456;
        int n = rem / 384, k = rem - n * 384;
        v = p.wout[k >> 7][n * 128 + (k & 127)];
    } else if (idx < 212992) v = p.w1[idx - 196608];
    else                     v = p.w2[idx - 212992];
    g_wh[idx] = __float2half(v);
}

// ---------------------------------------------------------------------------
// prep: xe = 2*x + px + py + pz, transpose (B,C,S) -> (token, C), fp16
// ---------------------------------------------------------------------------
__global__ __launch_bounds__(256) void prep_kernel(
    const float* __restrict__ x,  const float* __restrict__ px,
    const float* __restrict__ py, const float* __restrict__ pz)
{
    __shared__ float tile[64][130];
    int base = blockIdx.x * 64;
    int b    = base / SS;
    int sp0  = base % SS;

#pragma unroll
    for (int k = 0; k < 16; k++) {
        int e  = threadIdx.x + k * 256;
        int c  = e >> 5;
        int s2 = (e & 31) * 2;
        int spatial = sp0 + s2;
        float2 xv = *(const float2*)(x + (size_t)b * 128 * SS
                                       + (size_t)c * SS + spatial);
        int zi0 = spatial % 48, r0 = spatial / 48;
        int yi0 = r0 % 48,      xi0 = r0 / 48;
        int sp1 = spatial + 1;
        int zi1 = sp1 % 48,     r1 = sp1 / 48;
        int yi1 = r1 % 48,      xi1 = r1 / 48;
        tile[s2][c]     = 2.0f * xv.x + px[c * 48 + xi0] + py[c * 48 + yi0]
                        + pz[c * 48 + zi0];
        tile[s2 + 1][c] = 2.0f * xv.y + px[c * 48 + xi1] + py[c * 48 + yi1]
                        + pz[c * 48 + zi1];
    }
    __syncthreads();
#pragma unroll
    for (int k = 0; k < 16; k++) {
        int e  = threadIdx.x + k * 256;
        int s  = e >> 6;
        int c2 = (e & 63) * 2;
        *(__half2*)(g_xe + (size_t)(base + s) * 128 + c2) =
            __floats2half2_rn(tile[s][c2], tile[s][c2 + 1]);
    }
}

// ---------------------------------------------------------------------------
// fused QKV + attention: grid (288, 3 axes); 512 threads = 2 warp-groups.
// Warp = head; Q in registers (scale folded); softmax in f16x2 (ex2.approx),
// norm deferred to O. K/V warp-private smem; group sync via named barriers.
// ---------------------------------------------------------------------------
#define ATTN3_SMEM 221184
#define EXP2_SCALE 0.36067376022224085f   // 0.25 * log2(e)

__global__ __launch_bounds__(512, 1) void attn3_kernel()
{
    extern __shared__ __align__(16) char smc[];
    unsigned sbase = (unsigned)__cvta_generic_to_shared(smc);
    const unsigned sW = sbase;

    int tid  = threadIdx.x;
    int gid  = tid >> 8;
    int gtid = tid & 255;
    int lane = tid & 31;
    int h    = (gtid >> 5);
    int g    = lane >> 2, t = lane & 3;

    unsigned gA  = sbase + 98304 + (unsigned)gid * 61440;
    unsigned gKV = gA + 24576;
    char*   KVc  = smc + 98304 + gid * 61440 + 24576;
    __half* Os   = (__half*)KVc;

    int axis = blockIdx.y;
    int stride = (axis == 0) ? 2304 : (axis == 1 ? 48 : 1);

    const __half* Wsrc = g_wh + (size_t)axis * 49152;
#pragma unroll
    for (int i = 0; i < 12; i++) {
        int idx = tid + i * 512;
        int row = idx >> 4, seg = idx & 15;
        cpa16_s(sW + row * 256 + (unsigned)((seg * 16) ^ ((row & 7) << 4)),
                Wsrc + (size_t)row * 128 + seg * 8);
    }
    CP_COMMIT();

#define BASE_OF(sq, bs) do {                                                  \
        int b_ = (sq) / 2304, rr_ = (sq) % 2304;                              \
        int o1_ = rr_ / 48, o2_ = rr_ % 48;                                   \
        if (axis == 0)      bs = (long)b_ * SS + o1_ * 48 + o2_;              \
        else if (axis == 1) bs = (long)b_ * SS + o1_ * 2304 + o2_;            \
        else                bs = (long)b_ * SS + o1_ * 2304 + (long)o2_ * 48; \
    } while (0)

#define STAGE_A(bs, buf) do {                                                 \
        _Pragma("unroll")                                                     \
        for (int it_ = 0; it_ < 3; it_++) {                                   \
            int idx_ = gtid + it_ * 256;                                      \
            int row_ = idx_ >> 4, seg_ = idx_ & 15;                           \
            cpa16_s(gA + (buf) * 12288 + row_ * 256                           \
                    + (unsigned)((seg_ * 16) ^ ((row_ & 7) << 4)),            \
                    g_xe + (size_t)((bs) + (long)row_ * stride) * 128         \
                    + seg_ * 8);                                              \
        }                                                                     \
    } while (0)

    int seqbase = blockIdx.x * 16 + gid;
    { long bs0; BASE_OF(seqbase, bs0); STAGE_A(bs0, 0); }
    CP_COMMIT();
    CP_WAIT1();
    __syncthreads();

    unsigned hiA = (unsigned)((lane >> 4) << 4);
    unsigned xA  = (unsigned)((lane & 7) << 4);
    int raL  = lane & 15;
    int rbL  = ((lane & 16) >> 1) + (lane & 7);
    unsigned hiB = (unsigned)(((lane >> 3) & 1) << 4);
    unsigned xB  = (unsigned)((lane & 7) << 4);
    int barid = gid + 1;

    for (int i = 0; i < 8; i++) {
        long bs; BASE_OF(seqbase + 2 * i, bs);
        if (i + 1 < 8) {
            long bn; BASE_OF(seqbase + 2 * (i + 1), bn);
            STAGE_A(bn, (i + 1) & 1);
            CP_COMMIT(); CP_WAIT1();
        } else {
            CP_WAIT0();
        }
        NBAR(barid);

        // ---- GEMM: warp computes its head's q|k|v (48 cols), M=48, K=128 --
        unsigned sAc = gA + (unsigned)((i & 1) * 12288);
        float acc[3][6][4];
#pragma unroll
        for (int mt = 0; mt < 3; mt++)
#pragma unroll
            for (int nt = 0; nt < 6; nt++)
#pragma unroll
                for (int q = 0; q < 4; q++) acc[mt][nt][q] = 0.f;

#pragma unroll
        for (int kt = 0; kt < 8; kt++) {
            unsigned a[3][4];
#pragma unroll
            for (int mt = 0; mt < 3; mt++)
                LDSM4(a[mt], sAc + (unsigned)((mt * 16 + raL) * 256)
                             + (((unsigned)(kt * 32) + hiA) ^ xA));
#pragma unroll
            for (int np = 0; np < 3; np++) {
                int rowb = np * 128 + h * 16 + rbL;
                unsigned b[4];
                LDSM4(b, sW + (unsigned)(rowb * 256)
                         + (((unsigned)(kt * 32) + hiB) ^ xB));
#pragma unroll
                for (int mt = 0; mt < 3; mt++) {
                    MMA16(acc[mt][2 * np],     a[mt], b[0], b[1]);
                    MMA16(acc[mt][2 * np + 1], a[mt], b[2], b[3]);
                }
            }
        }

        // ---- Q: C-frag -> A-frag repack with softmax scale folded in ----
        unsigned qf[3][4];
#pragma unroll
        for (int mt = 0; mt < 3; mt++) {
            qf[mt][0] = h2u(acc[mt][0][0] * EXP2_SCALE, acc[mt][0][1] * EXP2_SCALE);
            qf[mt][1] = h2u(acc[mt][0][2] * EXP2_SCALE, acc[mt][0][3] * EXP2_SCALE);
            qf[mt][2] = h2u(acc[mt][1][0] * EXP2_SCALE, acc[mt][1][1] * EXP2_SCALE);
            qf[mt][3] = h2u(acc[mt][1][2] * EXP2_SCALE, acc[mt][1][3] * EXP2_SCALE);
        }
        // ---- K,V -> warp-private smem (48B rows) ----
#pragma unroll
        for (int np = 1; np < 3; np++)
#pragma unroll
            for (int nts = 0; nts < 2; nts++) {
                int nt = np * 2 + nts;
                char* dst = KVc + (np - 1) * 18432 + h * 2304
                          + (nts * 8 + 2 * t) * 2;
#pragma unroll
                for (int mt = 0; mt < 3; mt++) {
                    int r0 = mt * 16 + g;
                    *(__half2*)(dst + r0 * 48) =
                        __floats2half2_rn(acc[mt][nt][0], acc[mt][nt][1]);
                    *(__half2*)(dst + (r0 + 8) * 48) =
                        __floats2half2_rn(acc[mt][nt][2], acc[mt][nt][3]);
                }
            }
        __syncwarp();

        // ---- scores S = Qs @ K^T (Q pre-scaled into exp2 domain) ----
        unsigned Kb = gKV + (unsigned)(h * 2304);
        unsigned Vb = Kb + 18432u;
        float s[3][6][4];
#pragma unroll
        for (int mt = 0; mt < 3; mt++)
#pragma unroll
            for (int nt = 0; nt < 6; nt++)
#pragma unroll
                for (int q = 0; q < 4; q++) s[mt][nt][q] = 0.f;
#pragma unroll
        for (int nt2 = 0; nt2 < 3; nt2++) {
            unsigned bb[4];
            LDSM4(bb, Kb + (unsigned)((nt2 * 16 + rbL) * 48) + hiB);
#pragma unroll
            for (int mt = 0; mt < 3; mt++) {
                MMA16(s[mt][2 * nt2],     qf[mt], bb[0], bb[1]);
                MMA16(s[mt][2 * nt2 + 1], qf[mt], bb[2], bb[3]);
            }
        }

        // ---- pack raw scores to A-frag half2s, exp2 in f16x2 ----
        unsigned pa[3][3][4];
#pragma unroll
        for (int kt = 0; kt < 3; kt++)
#pragma unroll
            for (int mt = 0; mt < 3; mt++) {
                pa[kt][mt][0] = h2u(s[mt][2 * kt][0],     s[mt][2 * kt][1]);
                pa[kt][mt][1] = h2u(s[mt][2 * kt][2],     s[mt][2 * kt][3]);
                pa[kt][mt][2] = h2u(s[mt][2 * kt + 1][0], s[mt][2 * kt + 1][1]);
                pa[kt][mt][3] = h2u(s[mt][2 * kt + 1][2], s[mt][2 * kt + 1][3]);
            }
#pragma unroll
        for (int kt = 0; kt < 3; kt++)
#pragma unroll
            for (int mt = 0; mt < 3; mt++)
#pragma unroll
                for (int q = 0; q < 4; q++)
                    EX2H2(pa[kt][mt][q]);

        // ---- row sums (half2 tree), norm deferred to O ----
        float inv[3][2];
#pragma unroll
        for (int mt = 0; mt < 3; mt++) {
            __half2 h0 = __hadd2(u2h(pa[0][mt][0]), u2h(pa[0][mt][2]));
            h0 = __hadd2(h0, __hadd2(u2h(pa[1][mt][0]), u2h(pa[1][mt][2])));
            h0 = __hadd2(h0, __hadd2(u2h(pa[2][mt][0]), u2h(pa[2][mt][2])));
            __half2 h1 = __hadd2(u2h(pa[0][mt][1]), u2h(pa[0][mt][3]));
            h1 = __hadd2(h1, __hadd2(u2h(pa[1][mt][1]), u2h(pa[1][mt][3])));
            h1 = __hadd2(h1, __hadd2(u2h(pa[2][mt][1]), u2h(pa[2][mt][3])));
            float s0 = __low2float(h0) + __high2float(h0);
            float s1 = __low2float(h1) + __high2float(h1);
            s0 += __shfl_xor_sync(0xffffffffu, s0, 1);
            s0 += __shfl_xor_sync(0xffffffffu, s0, 2);
            s1 += __shfl_xor_sync(0xffffffffu, s1, 1);
            s1 += __shfl_xor_sync(0xffffffffu, s1, 2);
            inv[mt][0] = 1.f / s0;
            inv[mt][1] = 1.f / s1;
        }

        // ---- O = P_unnorm @ V ----
        float o[3][2][4];
#pragma unroll
        for (int mt = 0; mt < 3; mt++)
#pragma unroll
            for (int nt = 0; nt < 2; nt++)
#pragma unroll
                for (int q = 0; q < 4; q++) o[mt][nt][q] = 0.f;
#pragma unroll
        for (int kt = 0; kt < 3; kt++) {
            unsigned vb[4];
            LDSM4T(vb, Vb + (unsigned)((kt * 16 + raL) * 48) + hiA);
#pragma unroll
            for (int mt = 0; mt < 3; mt++) {
                MMA16(o[mt][0], pa[kt][mt], vb[0], vb[1]);
                MMA16(o[mt][1], pa[kt][mt], vb[2], vb[3]);
            }
        }

        NBAR(barid);   // all group warps done reading K/V (Os aliases KV)

        // ---- normalize O, stage, coalesced group store ----
#pragma unroll
        for (int mt = 0; mt < 3; mt++)
#pragma unroll
            for (int nt = 0; nt < 2; nt++) {
                int col = h * 16 + nt * 8 + 2 * t;
                int r0 = mt * 16 + g;
                *(__half2*)(Os + r0 * 136 + col) =
                    __floats2half2_rn(o[mt][nt][0] * inv[mt][0],
                                      o[mt][nt][1] * inv[mt][0]);
                *(__half2*)(Os + (r0 + 8) * 136 + col) =
                    __floats2half2_rn(o[mt][nt][2] * inv[mt][1],
                                      o[mt][nt][3] * inv[mt][1]);
            }
        NBAR(barid);

#pragma unroll
        for (int it = 0; it < 3; it++) {
            int idx = gtid + it * 256;
            int row = idx >> 4, c = idx & 15;
            *(uint4*)(g_o + (size_t)(bs + (long)row * stride) * 384
                      + axis * 128 + c * 8) = *(const uint4*)(Os + row * 136 + c * 8);
        }
    }
#undef BASE_OF
#undef STAGE_A
}

// ---------------------------------------------------------------------------
// fused tail: outproj(+bias3+res) -> LN1 -> mlp1(relu) -> mlp2(+res) -> LN2
// -> transposed fp32 store. Register-resident LN (stats via quad shuffles +
// 2KB stats smem); w1/w2 staging overlapped with P1 epilogue.
// ---------------------------------------------------------------------------
#define FUSE_SMEM 102912

struct FP {
    const float *bo0, *bo1, *bo2, *b1, *b2, *lng, *lnb;
    float* out;
};

__global__ __launch_bounds__(256, 2) void fuse_kernel(FP p)
{
    extern __shared__ __align__(16) char smc[];
    unsigned sR = (unsigned)__cvta_generic_to_shared(smc);
    unsigned sX = sR + 68096;
    float* Ct = (float*)smc;
    float* st = (float*)(smc + 100864);    // stats: [row][nw][sum,sq] = 2KB

    int tid = threadIdx.x, w = tid >> 5, lane = tid & 31;
    int mw = w & 3, nw = w >> 2;
    int g = lane >> 2, t = lane & 3;
    long m0 = (long)blockIdx.x * 128;

    int rowA  = mw * 32 + (lane & 15);
    int rowB0 = nw * 64 + ((lane & 16) >> 1) + (lane & 7);
    unsigned hiA = (unsigned)((lane >> 4) << 4);
    unsigned hiB = (unsigned)(((lane >> 3) & 1) << 4);
    unsigned xA = (unsigned)((rowA & 7) << 4);
    unsigned xB = (unsigned)((rowB0 & 7) << 4);

    // ================= P1: outproj, A=g_o (lda 384), B=wout_cat, K=384 ======
    float acc[2][8][4];
#pragma unroll
    for (int mt = 0; mt < 2; mt++)
#pragma unroll
        for (int nt = 0; nt < 8; nt++)
#pragma unroll
            for (int i = 0; i < 4; i++) acc[mt][nt][i] = 0.f;
    {
        unsigned sA = sR, sB = sR + 32768;
        const __half* Ap = g_o;
        const __half* Bp = g_wh + 147456;

#define STAGE1(c, buf) do {                                                   \
        int k0_ = (c) * 64;                                                   \
        _Pragma("unroll")                                                     \
        for (int i_ = 0; i_ < 4; i_++) {                                      \
            int idx_ = tid + 256 * i_;                                        \
            int row_ = idx_ >> 3, seg_ = idx_ & 7;                            \
            unsigned dcol_ = (unsigned)((seg_ * 16) ^ ((row_ & 7) << 4));     \
            cpa16_s(sA + (buf) * 16384 + row_ * 128 + dcol_,                  \
                    Ap + (m0 + row_) * 384 + k0_ + seg_ * 8);                 \
            cpa16_s(sB + (buf) * 16384 + row_ * 128 + dcol_,                  \
                    Bp + (size_t)row_ * 384 + k0_ + seg_ * 8);                \
        }                                                                     \
    } while (0)

        STAGE1(0, 0); CP_COMMIT();
        for (int c = 0; c < 6; c++) {
            if (c + 1 < 6) { STAGE1(c + 1, (c + 1) & 1); CP_COMMIT(); CP_WAIT1(); }
            else           { CP_WAIT0(); }
            __syncthreads();
            unsigned baseA = sA + (c & 1) * 16384;
            unsigned baseB = sB + (c & 1) * 16384;
#pragma unroll
            for (int kt = 0; kt < 4; kt++) {
                unsigned a[2][4];
#pragma unroll
                for (int mt = 0; mt < 2; mt++)
                    LDSM4(a[mt], baseA + (rowA + mt * 16) * 128
                                 + (((unsigned)(kt * 32) + hiA) ^ xA));
#pragma unroll
                for (int np = 0; np < 4; np++) {
                    unsigned b[4];
                    LDSM4(b, baseB + (rowB0 + np * 16) * 128
                             + (((unsigned)(kt * 32) + hiB) ^ xB));
                    MMA16(acc[0][2 * np],     a[0], b[0], b[1]);
                    MMA16(acc[1][2 * np],     a[1], b[0], b[1]);
                    MMA16(acc[0][2 * np + 1], a[0], b[2], b[3]);
                    MMA16(acc[1][2 * np + 1], a[1], b[2], b[3]);
                }
            }
            __syncthreads();
        }
#undef STAGE1
    }

    // ---- stage w1/w2 early (P1 buffers free after final sync above) ----
    {
        const __half* w1p = g_wh + 196608;
        const __half* w2p = g_wh + 212992;
#pragma unroll
        for (int i = 0; i < 8; i++) {
            int idx = tid + i * 256;
            int row = idx >> 4, seg = idx & 15;
            unsigned dcol = (unsigned)((seg * 16) ^ ((row & 7) << 4));
            cpa16_s(sR + row * 256 + dcol, w1p + row * 128 + seg * 8);
            cpa16_s(sR + 32768 + row * 256 + dcol, w2p + row * 128 + seg * 8);
        }
        CP_COMMIT();
    }

    // ---- P1 epilogue in registers: acc += bias3 + g_xe residual ----
#pragma unroll
    for (int mt = 0; mt < 2; mt++)
#pragma unroll
        for (int nt = 0; nt < 8; nt++) {
            int cc = nw * 64 + nt * 8 + 2 * t;
            size_t tok = m0 + mw * 32 + mt * 16 + g;
            float b0 = p.bo0[cc] + p.bo1[cc] + p.bo2[cc];
            float b1v = p.bo0[cc + 1] + p.bo1[cc + 1] + p.bo2[cc + 1];
            float2 r0 = __half22float2(*(const __half2*)(g_xe + tok * 128 + cc));
            float2 r1 = __half22float2(*(const __half2*)(g_xe + (tok + 8) * 128 + cc));
            acc[mt][nt][0] += b0 + r0.x;
            acc[mt][nt][1] += b1v + r0.y;
            acc[mt][nt][2] += b0 + r1.x;
            acc[mt][nt][3] += b1v + r1.y;
        }

    // ---- LN1 stats from registers ----
#pragma unroll
    for (int mt = 0; mt < 2; mt++) {
        float s0 = 0, q0 = 0, s1 = 0, q1 = 0;
#pragma unroll
        for (int nt = 0; nt < 8; nt++) {
            s0 += acc[mt][nt][0] + acc[mt][nt][1];
            q0 += acc[mt][nt][0] * acc[mt][nt][0] + acc[mt][nt][1] * acc[mt][nt][1];
            s1 += acc[mt][nt][2] + acc[mt][nt][3];
            q1 += acc[mt][nt][2] * acc[mt][nt][2] + acc[mt][nt][3] * acc[mt][nt][3];
        }
        s0 += __shfl_xor_sync(0xffffffffu, s0, 1); s0 += __shfl_xor_sync(0xffffffffu, s0, 2);
        q0 += __shfl_xor_sync(0xffffffffu, q0, 1); q0 += __shfl_xor_sync(0xffffffffu, q0, 2);
        s1 += __shfl_xor_sync(0xffffffffu, s1, 1); s1 += __shfl_xor_sync(0xffffffffu, s1, 2);
        q1 += __shfl_xor_sync(0xffffffffu, q1, 1); q1 += __shfl_xor_sync(0xffffffffu, q1, 2);
        if (t == 0) {
            int r0 = mw * 32 + mt * 16 + g;
            st[r0 * 4 + nw * 2]           = s0;
            st[r0 * 4 + nw * 2 + 1]       = q0;
            st[(r0 + 8) * 4 + nw * 2]     = s1;
            st[(r0 + 8) * 4 + nw * 2 + 1] = q1;
        }
    }
    __syncthreads();

    // ---- LN1 normalize -> xln (fp16 swizzled, row 256B) ----
#pragma unroll
    for (int mt = 0; mt < 2; mt++) {
        int rl = mw * 32 + mt * 16 + g;
        float m0v = (st[rl * 4] + st[rl * 4 + 2]) * (1.f / 128.f);
        float v0  = (st[rl * 4 + 1] + st[rl * 4 + 3]) * (1.f / 128.f) - m0v * m0v;
        float rs0 = rsqrtf(v0 + 1e-5f);
        float m1v = (st[(rl + 8) * 4] + st[(rl + 8) * 4 + 2]) * (1.f / 128.f);
        float v1  = (st[(rl + 8) * 4 + 1] + st[(rl + 8) * 4 + 3]) * (1.f / 128.f) - m1v * m1v;
        float rs1 = rsqrtf(v1 + 1e-5f);
        unsigned sw0 = (unsigned)((rl & 7) << 4);
        unsigned sw1 = (unsigned)(((rl + 8) & 7) << 4);
#pragma unroll
        for (int nt = 0; nt < 8; nt++) {
            int cc = nw * 64 + nt * 8 + 2 * t;
            float g0 = p.lng[cc], g1 = p.lng[cc + 1];
            float bb0 = p.lnb[cc], bb1 = p.lnb[cc + 1];
            unsigned c2 = (unsigned)(2 * cc);
            *(__half2*)(smc + 68096 + rl * 256 + (c2 ^ sw0)) =
                __floats2half2_rn((acc[mt][nt][0] - m0v) * rs0 * g0 + bb0,
                                  (acc[mt][nt][1] - m0v) * rs0 * g1 + bb1);
            *(__half2*)(smc + 68096 + (rl + 8) * 256 + (c2 ^ sw1)) =
                __floats2half2_rn((acc[mt][nt][2] - m1v) * rs1 * g0 + bb0,
                                  (acc[mt][nt][3] - m1v) * rs1 * g1 + bb1);
        }
    }
    CP_WAIT0();
    __syncthreads();

    // ================= P2: h = relu(xln @ w1^T + b1), K=128 =================
    float acc2[2][8][4];
#pragma unroll
    for (int mt = 0; mt < 2; mt++)
#pragma unroll
        for (int nt = 0; nt < 8; nt++)
#pragma unroll
            for (int i = 0; i < 4; i++) acc2[mt][nt][i] = 0.f;

#pragma unroll
    for (int kt = 0; kt < 8; kt++) {
        unsigned a[2][4];
#pragma unroll
        for (int mt = 0; mt < 2; mt++)
            LDSM4(a[mt], sX + (rowA + mt * 16) * 256
                         + (((unsigned)(kt * 32) + hiA) ^ xA));
#pragma unroll
        for (int np = 0; np < 4; np++) {
            unsigned b[4];
            LDSM4(b, sR + (rowB0 + np * 16) * 256
                     + (((unsigned)(kt * 32) + hiB) ^ xB));
            MMA16(acc2[0][2 * np],     a[0], b[0], b[1]);
            MMA16(acc2[1][2 * np],     a[1], b[0], b[1]);
            MMA16(acc2[0][2 * np + 1], a[0], b[2], b[3]);
            MMA16(acc2[1][2 * np + 1], a[1], b[2], b[3]);
        }
    }
    __syncthreads();

    // h tile (fp16 swizzled, row 256B) at R1[0,32K)
#pragma unroll
    for (int mt = 0; mt < 2; mt++)
#pragma unroll
        for (int nt = 0; nt < 8; nt++) {
            int rl = mw * 32 + mt * 16 + g;
            int cc = nw * 64 + nt * 8 + 2 * t;
            float b0 = p.b1[cc], b1v = p.b1[cc + 1];
            unsigned c2 = (unsigned)(2 * cc);
            *(__half2*)(smc + rl * 256 + (c2 ^ (unsigned)((rl & 7) << 4))) =
                __floats2half2_rn(fmaxf(acc2[mt][nt][0] + b0, 0.f),
                                  fmaxf(acc2[mt][nt][1] + b1v, 0.f));
            *(__half2*)(smc + (rl + 8) * 256 + (c2 ^ (unsigned)(((rl + 8) & 7) << 4))) =
                __floats2half2_rn(fmaxf(acc2[mt][nt][2] + b0, 0.f),
                                  fmaxf(acc2[mt][nt][3] + b1v, 0.f));
        }
    __syncthreads();

    // ================= P3: y = h @ w2^T + b2 + xln, K=128 ===================
    float acc3[2][8][4];
#pragma unroll
    for (int mt = 0; mt < 2; mt++)
#pragma unroll
        for (int nt = 0; nt < 8; nt++)
#pragma unroll
            for (int i = 0; i < 4; i++) acc3[mt][nt][i] = 0.f;

#pragma unroll
    for (int kt = 0; kt < 8; kt++) {
        unsigned a[2][4];
#pragma unroll
        for (int mt = 0; mt < 2; mt++)
            LDSM4(a[mt], sR + (rowA + mt * 16) * 256
                         + (((unsigned)(kt * 32) + hiA) ^ xA));
#pragma unroll
        for (int np = 0; np < 4; np++) {
            unsigned b[4];
            LDSM4(b, sR + 32768 + (rowB0 + np * 16) * 256
                     + (((unsigned)(kt * 32) + hiB) ^ xB));
            MMA16(acc3[0][2 * np],     a[0], b[0], b[1]);
            MMA16(acc3[1][2 * np],     a[1], b[0], b[1]);
            MMA16(acc3[0][2 * np + 1], a[0], b[2], b[3]);
            MMA16(acc3[1][2 * np + 1], a[1], b[2], b[3]);
        }
    }

    // ---- P3 epilogue in registers: acc3 += b2 + xln residual ----
#pragma unroll
    for (int mt = 0; mt < 2; mt++)
#pragma unroll
        for (int nt = 0; nt < 8; nt++) {
            int rl = mw * 32 + mt * 16 + g;
            int cc = nw * 64 + nt * 8 + 2 * t;
            float b0 = p.b2[cc], b1v = p.b2[cc + 1];
            unsigned c2 = (unsigned)(2 * cc);
            __half2 r0 = *(const __half2*)(smc + 68096 + rl * 256
                                           + (c2 ^ (unsigned)((rl & 7) << 4)));
            __half2 r1 = *(const __half2*)(smc + 68096 + (rl + 8) * 256
                                           + (c2 ^ (unsigned)(((rl + 8) & 7) << 4)));
            float2 f0 = __half22float2(r0);
            float2 f1 = __half22float2(r1);
            acc3[mt][nt][0] += b0 + f0.x;
            acc3[mt][nt][1] += b1v + f0.y;
            acc3[mt][nt][2] += b0 + f1.x;
            acc3[mt][nt][3] += b1v + f1.y;
        }

    // ---- LN2 stats from registers ----
#pragma unroll
    for (int mt = 0; mt < 2; mt++) {
        float s0 = 0, q0 = 0, s1 = 0, q1 = 0;
#pragma unroll
        for (int nt = 0; nt < 8; nt++) {
            s0 += acc3[mt][nt][0] + acc3[mt][nt][1];
            q0 += acc3[mt][nt][0] * acc3[mt][nt][0] + acc3[mt][nt][1] * acc3[mt][nt][1];
            s1 += acc3[mt][nt][2] + acc3[mt][nt][3];
            q1 += acc3[mt][nt][2] * acc3[mt][nt][2] + acc3[mt][nt][3] * acc3[mt][nt][3];
        }
        s0 += __shfl_xor_sync(0xffffffffu, s0, 1); s0 += __shfl_xor_sync(0xffffffffu, s0, 2);
        q0 += __shfl_xor_sync(0xffffffffu, q0, 1); q0 += __shfl_xor_sync(0xffffffffu, q0, 2);
        s1 += __shfl_xor_sync(0xffffffffu, s1, 1); s1 += __shfl_xor_sync(0xffffffffu, s1, 2);
        q1 += __shfl_xor_sync(0xffffffffu, q1, 1); q1 += __shfl_xor_sync(0xffffffffu, q1, 2);
        if (t == 0) {
            int r0 = mw * 32 + mt * 16 + g;
            st[r0 * 4 + nw * 2]           = s0;
            st[r0 * 4 + nw * 2 + 1]       = q0;
            st[(r0 + 8) * 4 + nw * 2]     = s1;
            st[(r0 + 8) * 4 + nw * 2 + 1] = q1;
        }
    }
    __syncthreads();   // stats ready; also h/w2 reads done -> Ct may overwrite

    // ---- LN2 normalize -> Ct fp32 (133 stride) ----
#pragma unroll
    for (int mt = 0; mt < 2; mt++) {
        int rl = mw * 32 + mt * 16 + g;
        float m0v = (st[rl * 4] + st[rl * 4 + 2]) * (1.f / 128.f);
        float v0  = (st[rl * 4 + 1] + st[rl * 4 + 3]) * (1.f / 128.f) - m0v * m0v;
        float rs0 = rsqrtf(v0 + 1e-5f);
        float m1v = (st[(rl + 8) * 4] + st[(rl + 8) * 4 + 2]) * (1.f / 128.f);
        float v1  = (st[(rl + 8) * 4 + 1] + st[(rl + 8) * 4 + 3]) * (1.f / 128.f) - m1v * m1v;
        float rs1 = rsqrtf(v1 + 1e-5f);
#pragma unroll
        for (int nt = 0; nt < 8; nt++) {
            int cc = nw * 64 + nt * 8 + 2 * t;
            float g0 = p.lng[cc], g1 = p.lng[cc + 1];
            float bb0 = p.lnb[cc], bb1 = p.lnb[cc + 1];
            Ct[rl * 133 + cc]           = (acc3[mt][nt][0] - m0v) * rs0 * g0 + bb0;
            Ct[rl * 133 + cc + 1]       = (acc3[mt][nt][1] - m0v) * rs0 * g1 + bb1;
            Ct[(rl + 8) * 133 + cc]     = (acc3[mt][nt][2] - m1v) * rs1 * g0 + bb0;
            Ct[(rl + 8) * 133 + cc + 1] = (acc3[mt][nt][3] - m1v) * rs1 * g1 + bb1;
        }
    }
    __syncthreads();

    // transposed fp32 store to (B,C,X,Y,Z)
    int  bi  = (int)(m0 / SS);
    long sp0 = m0 % SS;
    float* outp = p.out + (size_t)bi * 128 * SS + sp0;
    for (int e = tid; e < 128 * 128; e += 256) {
        int cc = e >> 7, ss = e & 127;
        outp[(size_t)cc * SS + ss] = Ct[ss * 133 + cc];
    }
}

// ---------------------------------------------------------------------------
// launch
// ---------------------------------------------------------------------------
extern "C" void kernel_launch(void* const* d_in, const int* in_sizes, int n_in,
                              void* d_out, int out_size)
{
    (void)in_sizes; (void)n_in; (void)out_size;
    const float* x    = (const float*)d_in[0];
    const float* px   = (const float*)d_in[1];
    const float* py   = (const float*)d_in[2];
    const float* pz   = (const float*)d_in[3];

    cudaFuncSetAttribute((const void*)attn3_kernel,
                         cudaFuncAttributeMaxDynamicSharedMemorySize, ATTN3_SMEM);
    cudaFuncSetAttribute((const void*)fuse_kernel,
                         cudaFuncAttributeMaxDynamicSharedMemorySize, FUSE_SMEM);

    WP wp;
    for (int a = 0; a < 3; a++) {
        wp.wq[a]   = (const float*)d_in[4 + 4 * a];
        wp.wkv[a]  = (const float*)d_in[5 + 4 * a];
        wp.wout[a] = (const float*)d_in[6 + 4 * a];
    }
    wp.w1 = (const float*)d_in[18];
    wp.w2 = (const float*)d_in[20];
    wconv_kernel<<<896, 256>>>(wp);

    prep_kernel<<<NT / 64, 256>>>(x, px, py, pz);

    attn3_kernel<<<dim3(288, 3), 512, ATTN3_SMEM>>>();

    FP fp;
    fp.bo0 = (const float*)d_in[7];
    fp.bo1 = (const float*)d_in[11];
    fp.bo2 = (const float*)d_in[15];
    fp.b1  = (const float*)d_in[19];
    fp.b2  = (const float*)d_in[21];
    fp.lng = (const float*)d_in[16];
    fp.lnb = (const float*)d_in[17];
    fp.out = (float*)d_out;
    fuse_kernel<<<NT / 128, 256, FUSE_SMEM>>>(fp);
}